// round 7
// baseline (speedup 1.0000x reference)
#include <cuda_runtime.h>
#include <cuda_bf16.h>
#include <math.h>
#include <stdint.h>

typedef unsigned long long ull;

// ---------------- scratch (static device globals; no allocation) ----------------
__device__ float g_pre[2u * 512u * 32u * 512u];   // [dir][t][b][c] 64MB
__device__ float g_hs[512u * 32u * 1024u];        // [t][b][dir*512+c] 64MB

// ---------------- f32x2 helpers ----------------
__device__ __forceinline__ ull ffma2(ull a, ull b, ull c) {
    ull d;
    asm("fma.rn.f32x2 %0, %1, %2, %3;" : "=l"(d) : "l"(a), "l"(b), "l"(c));
    return d;
}
__device__ __forceinline__ ull pack2(float x) {
    ull d;
    asm("mov.b64 %0, {%1, %1};" : "=l"(d) : "f"(x));
    return d;
}
__device__ __forceinline__ ull packab(float a, float b) {
    ull d;
    asm("mov.b64 %0, {%1, %2};" : "=l"(d) : "f"(a), "f"(b));
    return d;
}
__device__ __forceinline__ float2 unpack2(ull v) {
    float2 r;
    asm("mov.b64 {%0, %1}, %2;" : "=f"(r.x), "=f"(r.y) : "l"(v));
    return r;
}
__device__ __forceinline__ uint32_t smem_u32(const void* p) {
    uint32_t a;
    asm("{ .reg .u64 t; cvta.to.shared.u64 t, %1; cvt.u32.u64 %0, t; }"
        : "=r"(a) : "l"(p));
    return a;
}
// mbarrier parity wait, acquire at cluster scope (orders peers' DSMEM stores)
__device__ __forceinline__ void mbar_wait_acq_cluster(uint32_t addr, int parity) {
    uint32_t done;
    asm volatile(
        "{\n\t.reg .pred p;\n\t"
        "mbarrier.try_wait.parity.acquire.cluster.shared::cta.b64 p, [%1], %2;\n\t"
        "selp.b32 %0, 1, 0, p;\n\t}"
        : "=r"(done) : "r"(addr), "r"((uint32_t)parity) : "memory");
    if (!done) {
        asm volatile(
            "{\n\t.reg .pred P1;\n\t"
            "W_%=:\n\t"
            "mbarrier.try_wait.parity.acquire.cluster.shared::cta.b64 P1, [%0], %1;\n\t"
            "@P1 bra.uni D_%=;\n\t"
            "bra.uni W_%=;\n\t"
            "D_%=:\n\t}"
            :: "r"(addr), "r"((uint32_t)parity) : "memory");
    }
}

// =================================================================================
// Kernel 1: pre-projection GEMM (double-buffered smem)
// =================================================================================
__global__ __launch_bounds__(256) void pre_gemm(
    const float* __restrict__ X,
    const float* __restrict__ Wf, const float* __restrict__ bf,
    const float* __restrict__ Wb, const float* __restrict__ bb)
{
    __shared__ float As[2][8][132];
    __shared__ float Bs[2][8][136];

    const int tid = threadIdx.x;
    const int m0 = blockIdx.y * 128;
    const int n0 = blockIdx.x * 128;
    const int dir = n0 >> 9;
    const int c0 = n0 & 511;
    const float* Bmat = dir ? Wb : Wf;
    const float* bias = dir ? bb : bf;

    const int ar  = tid >> 1;
    const int akq = (tid & 1) * 4;
    const int am  = m0 + ar;
    const float* Arow = X + ((size_t)(am & 31) * 512 + (size_t)(am >> 5)) * 512;

    const int bkk = tid >> 5;
    const int bnq = (tid & 31) * 4;

    const int ty = tid >> 4;
    const int tx = tid & 15;

    ull acc[4][8];
    #pragma unroll
    for (int i = 0; i < 4; ++i)
        #pragma unroll
        for (int j = 0; j < 8; ++j) acc[i][j] = 0ull;

    {
        float4 av = *(const float4*)(Arow + akq);
        float4 bv = *(const float4*)(Bmat + (size_t)bkk * 512 + c0 + bnq);
        As[0][akq + 0][ar] = av.x;
        As[0][akq + 1][ar] = av.y;
        As[0][akq + 2][ar] = av.z;
        As[0][akq + 3][ar] = av.w;
        *(float4*)&Bs[0][bkk][bnq] = bv;
    }
    __syncthreads();

    int buf = 0;
    for (int k0 = 0; k0 < 512; k0 += 8) {
        float4 av, bv;
        const bool more = (k0 + 8 < 512);
        if (more) {
            av = *(const float4*)(Arow + k0 + 8 + akq);
            bv = *(const float4*)(Bmat + (size_t)(k0 + 8 + bkk) * 512 + c0 + bnq);
        }

        #pragma unroll
        for (int k = 0; k < 8; ++k) {
            ulonglong2 a01 = *(const ulonglong2*)&As[buf][k][ty * 8];
            ulonglong2 a23 = *(const ulonglong2*)&As[buf][k][ty * 8 + 4];
            float4 bA = *(const float4*)&Bs[buf][k][tx * 8];
            float4 bB = *(const float4*)&Bs[buf][k][tx * 8 + 4];
            ull bd[8];
            bd[0] = pack2(bA.x); bd[1] = pack2(bA.y);
            bd[2] = pack2(bA.z); bd[3] = pack2(bA.w);
            bd[4] = pack2(bB.x); bd[5] = pack2(bB.y);
            bd[6] = pack2(bB.z); bd[7] = pack2(bB.w);
            #pragma unroll
            for (int j = 0; j < 8; ++j) {
                acc[0][j] = ffma2(a01.x, bd[j], acc[0][j]);
                acc[1][j] = ffma2(a01.y, bd[j], acc[1][j]);
                acc[2][j] = ffma2(a23.x, bd[j], acc[2][j]);
                acc[3][j] = ffma2(a23.y, bd[j], acc[3][j]);
            }
        }

        if (more) {
            int nb = buf ^ 1;
            As[nb][akq + 0][ar] = av.x;
            As[nb][akq + 1][ar] = av.y;
            As[nb][akq + 2][ar] = av.z;
            As[nb][akq + 3][ar] = av.w;
            *(float4*)&Bs[nb][bkk][bnq] = bv;
            __syncthreads();
            buf = nb;
        }
    }

    const int cg = c0 + tx * 8;
    float4 bl = *(const float4*)(bias + cg);
    float4 bh = *(const float4*)(bias + cg + 4);
    #pragma unroll
    for (int mp = 0; mp < 4; ++mp) {
        float2 v[8];
        #pragma unroll
        for (int j = 0; j < 8; ++j) v[j] = unpack2(acc[mp][j]);
        #pragma unroll
        for (int p = 0; p < 2; ++p) {
            int m = m0 + ty * 8 + mp * 2 + p;
            int tt = m >> 5, bb2 = m & 31;
            float* dst = g_pre + ((size_t)dir * 512 + tt) * 16384 + (size_t)bb2 * 512 + cg;
            float4 o0, o1;
            o0.x = (p ? v[0].y : v[0].x) + bl.x;
            o0.y = (p ? v[1].y : v[1].x) + bl.y;
            o0.z = (p ? v[2].y : v[2].x) + bl.z;
            o0.w = (p ? v[3].y : v[3].x) + bl.w;
            o1.x = (p ? v[4].y : v[4].x) + bh.x;
            o1.y = (p ? v[5].y : v[5].x) + bh.y;
            o1.z = (p ? v[6].y : v[6].x) + bh.z;
            o1.w = (p ? v[7].y : v[7].x) + bh.w;
            *(float4*)dst = o0;
            *(float4*)(dst + 4) = o1;
        }
    }
}

// =================================================================================
// Kernel 2: persistent bidirectional recurrence (v7 — DSMEM allgather)
//   128 CTAs = 16 clusters of 8. Cluster = (dir, 4-batch group); rank = 64-col slice.
//   512 threads: (c 0..63, ks 0..7); Wh[ks*64..+63][c0+c] in 32 f32x2 regs.
//   Per step: compute from local s_h buffer (filled by peers via DSMEM last step),
//   8-way reduce, tanh, scatter h to all 8 peers' next buffer (st.shared::cluster),
//   remote mbarrier arrive; consumers try_wait (acquire.cluster).
// =================================================================================
__global__ __launch_bounds__(512) void recur_kernel(
    const float* __restrict__ Wf, const float* __restrict__ Wb)
{
    __shared__ float s_h2[2][4 * 520];   // double-buffered group h [4 batches][512+8]
    __shared__ float s_red[8 * 256];     // [ks][b*64+c]
    __shared__ unsigned long long s_mbar[2];

    const int tid = threadIdx.x;
    const int bx  = blockIdx.x;
    const int cid = bx >> 3;                // cluster 0..15
    const int dir = cid & 1;
    const int grp = cid >> 1;               // 0..7 (4 batches)
    const int sl  = bx & 7;                 // cluster rank = col slice
    const int c0  = sl * 64;
    const int bgl = grp * 4;
    const float* W = dir ? Wb : Wf;

    const int c  = tid & 63;
    const int ks = tid >> 6;

    // Wh column (c0+c), k in [ks*64, ks*64+64) -> 32 f32x2 regs
    ull wreg[16][2];
    #pragma unroll
    for (int j = 0; j < 16; ++j) {
        int k = ks * 64 + j * 4;
        const float* wp = W + (size_t)(512 + k) * 512 + c0 + c;
        wreg[j][0] = packab(wp[0],    wp[512]);
        wreg[j][1] = packab(wp[1024], wp[1536]);
    }

    // reduce/scatter map (tid < 256): batch rb, col rc
    const int rb = tid >> 6;
    const int rc = tid & 63;

    const uint32_t mb0 = smem_u32(&s_mbar[0]);
    const uint32_t mb1 = smem_u32(&s_mbar[1]);
    const uint32_t hb0 = smem_u32(&s_h2[0][0]);
    const uint32_t hb1 = smem_u32(&s_h2[1][0]);

    if (tid == 0) {
        asm volatile("mbarrier.init.shared.b64 [%0], 8;" :: "r"(mb0) : "memory");
        asm volatile("mbarrier.init.shared.b64 [%0], 8;" :: "r"(mb1) : "memory");
    }
    __syncthreads();
    asm volatile("barrier.cluster.arrive.aligned;" ::: "memory");
    asm volatile("barrier.cluster.wait.aligned;"   ::: "memory");

    int ph0 = 0, ph1 = 0;

    // first step's pre-activation
    float pre = 0.f;
    {
        const int t0 = dir ? 511 : 0;
        if (tid < 256)
            pre = __ldcg(&g_pre[((size_t)dir * 512 + t0) * 16384 +
                                (size_t)(bgl + rb) * 512 + c0 + rc]);
    }

    for (int s = 0; s < 512; ++s) {
        const int t = dir ? (511 - s) : s;

        float hval = 0.f;
        if (s == 0) {
            if (tid < 256) hval = tanhf(pre);
        } else {
            // wait for peers' h (buffer parity s&1)
            const uint32_t mb = (s & 1) ? mb1 : mb0;
            if (s & 1) { mbar_wait_acq_cluster(mb, ph1); }
            else       { mbar_wait_acq_cluster(mb, ph0); }

            const float* hbuf = s_h2[s & 1];
            ull acc[4] = {0ull, 0ull, 0ull, 0ull};
            #pragma unroll
            for (int b = 0; b < 4; ++b) {
                const ulonglong2* hp = (const ulonglong2*)&hbuf[b * 520 + ks * 64];
                #pragma unroll
                for (int j = 0; j < 16; ++j) {
                    ulonglong2 h2 = hp[j];
                    acc[b] = ffma2(h2.x, wreg[j][0], acc[b]);
                    acc[b] = ffma2(h2.y, wreg[j][1], acc[b]);
                }
            }
            if (s & 1) ph1 ^= 1; else ph0 ^= 1;

            #pragma unroll
            for (int b = 0; b < 4; ++b) {
                float2 p = unpack2(acc[b]);
                s_red[ks * 256 + b * 64 + c] = p.x + p.y;
            }
            __syncthreads();

            if (tid < 256) {
                float sum = pre;
                #pragma unroll
                for (int k8 = 0; k8 < 8; ++k8) sum += s_red[k8 * 256 + tid];
                hval = tanhf(sum);
            }
        }

        if (tid < 256)
            __stcg(&g_hs[((size_t)t * 32 + bgl + rb) * 1024 +
                         dir * 512 + c0 + rc], hval);

        if (s < 511) {
            // scatter hval into every cluster CTA's next buffer
            if (tid < 256) {
                const uint32_t base = ((s + 1) & 1) ? hb1 : hb0;
                const uint32_t off = base + (uint32_t)((rb * 520 + c0 + rc) * 4);
                #pragma unroll
                for (int r = 0; r < 8; ++r) {
                    uint32_t ra;
                    asm("mapa.shared::cluster.u32 %0, %1, %2;"
                        : "=r"(ra) : "r"(off), "r"(r));
                    asm volatile("st.shared::cluster.f32 [%0], %1;"
                                 :: "r"(ra), "f"(hval) : "memory");
                }
            }
            __syncthreads();   // all scatter stores issued before arrives
            if (tid < 8) {
                const uint32_t mbn = ((s + 1) & 1) ? mb1 : mb0;
                uint32_t ra;
                asm("mapa.shared::cluster.u32 %0, %1, %2;"
                    : "=r"(ra) : "r"(mbn), "r"(tid));
                asm volatile("mbarrier.arrive.release.cluster.shared::cluster.b64 _, [%0];"
                             :: "r"(ra) : "memory");
            }
            // prefetch next step's pre (independent of the wait)
            const int tn = dir ? (510 - s) : (s + 1);
            if (tid < 256)
                pre = __ldcg(&g_pre[((size_t)dir * 512 + tn) * 16384 +
                                    (size_t)(bgl + rb) * 512 + c0 + rc]);
        }
    }
}

// =================================================================================
// Kernel 3: output GEMM (double-buffered smem)
// =================================================================================
__global__ __launch_bounds__(256) void out_gemm(
    const float* __restrict__ Wo, const float* __restrict__ bo,
    float* __restrict__ out)
{
    __shared__ float As[2][8][132];
    __shared__ float Bs[2][8][136];

    const int tid = threadIdx.x;
    const int m0 = blockIdx.y * 128;
    const int n0 = blockIdx.x * 128;

    const int ar  = tid >> 1;
    const int akq = (tid & 1) * 4;
    const float* Arow = g_hs + (size_t)(m0 + ar) * 1024;

    const int bkk = tid >> 5;
    const int bnq = (tid & 31) * 4;

    const int ty = tid >> 4;
    const int tx = tid & 15;

    ull acc[4][8];
    #pragma unroll
    for (int i = 0; i < 4; ++i)
        #pragma unroll
        for (int j = 0; j < 8; ++j) acc[i][j] = 0ull;

    {
        float4 av = *(const float4*)(Arow + akq);
        float4 bv = *(const float4*)(Wo + (size_t)bkk * 512 + n0 + bnq);
        As[0][akq + 0][ar] = av.x;
        As[0][akq + 1][ar] = av.y;
        As[0][akq + 2][ar] = av.z;
        As[0][akq + 3][ar] = av.w;
        *(float4*)&Bs[0][bkk][bnq] = bv;
    }
    __syncthreads();

    int buf = 0;
    for (int k0 = 0; k0 < 1024; k0 += 8) {
        float4 av, bv;
        const bool more = (k0 + 8 < 1024);
        if (more) {
            av = *(const float4*)(Arow + k0 + 8 + akq);
            bv = *(const float4*)(Wo + (size_t)(k0 + 8 + bkk) * 512 + n0 + bnq);
        }

        #pragma unroll
        for (int k = 0; k < 8; ++k) {
            ulonglong2 a01 = *(const ulonglong2*)&As[buf][k][ty * 8];
            ulonglong2 a23 = *(const ulonglong2*)&As[buf][k][ty * 8 + 4];
            float4 bA = *(const float4*)&Bs[buf][k][tx * 8];
            float4 bB = *(const float4*)&Bs[buf][k][tx * 8 + 4];
            ull bd[8];
            bd[0] = pack2(bA.x); bd[1] = pack2(bA.y);
            bd[2] = pack2(bA.z); bd[3] = pack2(bA.w);
            bd[4] = pack2(bB.x); bd[5] = pack2(bB.y);
            bd[6] = pack2(bB.z); bd[7] = pack2(bB.w);
            #pragma unroll
            for (int j = 0; j < 8; ++j) {
                acc[0][j] = ffma2(a01.x, bd[j], acc[0][j]);
                acc[1][j] = ffma2(a01.y, bd[j], acc[1][j]);
                acc[2][j] = ffma2(a23.x, bd[j], acc[2][j]);
                acc[3][j] = ffma2(a23.y, bd[j], acc[3][j]);
            }
        }

        if (more) {
            int nb = buf ^ 1;
            As[nb][akq + 0][ar] = av.x;
            As[nb][akq + 1][ar] = av.y;
            As[nb][akq + 2][ar] = av.z;
            As[nb][akq + 3][ar] = av.w;
            *(float4*)&Bs[nb][bkk][bnq] = bv;
            __syncthreads();
            buf = nb;
        }
    }

    const int og = n0 + tx * 8;
    float4 bl = *(const float4*)(bo + og);
    float4 bh = *(const float4*)(bo + og + 4);
    #pragma unroll
    for (int mp = 0; mp < 4; ++mp) {
        float2 v[8];
        #pragma unroll
        for (int j = 0; j < 8; ++j) v[j] = unpack2(acc[mp][j]);
        #pragma unroll
        for (int p = 0; p < 2; ++p) {
            int m = m0 + ty * 8 + mp * 2 + p;
            int tt = m >> 5, bb2 = m & 31;
            float* dst = out + ((size_t)bb2 * 512 + tt) * 512 + og;
            float4 o0, o1;
            o0.x = (p ? v[0].y : v[0].x) + bl.x;
            o0.y = (p ? v[1].y : v[1].x) + bl.y;
            o0.z = (p ? v[2].y : v[2].x) + bl.z;
            o0.w = (p ? v[3].y : v[3].x) + bl.w;
            o1.x = (p ? v[4].y : v[4].x) + bh.x;
            o1.y = (p ? v[5].y : v[5].x) + bh.y;
            o1.z = (p ? v[6].y : v[6].x) + bh.z;
            o1.w = (p ? v[7].y : v[7].x) + bh.w;
            *(float4*)dst = o0;
            *(float4*)(dst + 4) = o1;
        }
    }
}

// =================================================================================
extern "C" void kernel_launch(void* const* d_in, const int* in_sizes, int n_in,
                              void* d_out, int out_size)
{
    const float* X  = (const float*)d_in[0];
    const float* Wf = (const float*)d_in[1];
    const float* bf = (const float*)d_in[2];
    const float* Wb = (const float*)d_in[3];
    const float* bb = (const float*)d_in[4];
    const float* Wo = (const float*)d_in[5];
    const float* bo = (const float*)d_in[6];
    float* out = (float*)d_out;

    pre_gemm<<<dim3(8, 128), 256>>>(X, Wf, bf, Wb, bb);

    {
        cudaLaunchConfig_t cfg = {};
        cfg.gridDim  = dim3(128, 1, 1);
        cfg.blockDim = dim3(512, 1, 1);
        cfg.dynamicSmemBytes = 0;
        cudaLaunchAttribute attrs[1];
        attrs[0].id = cudaLaunchAttributeClusterDimension;
        attrs[0].val.clusterDim = {8, 1, 1};
        cfg.attrs = attrs;
        cfg.numAttrs = 1;
        cudaLaunchKernelEx(&cfg, recur_kernel, Wf, Wb);
    }

    out_gemm<<<dim3(4, 128), 256>>>(Wo, bo, out);
}

// round 8
// speedup vs baseline: 1.0330x; 1.0330x over previous
#include <cuda_runtime.h>
#include <cuda_bf16.h>
#include <math.h>
#include <stdint.h>

typedef unsigned long long ull;

// ---------------- scratch (static device globals; no allocation) ----------------
__device__ float g_pre[2u * 512u * 32u * 512u];   // [dir][t][b][c] 64MB
__device__ float g_hs[512u * 32u * 1024u];        // [t][b][dir*512+c] 64MB
__device__ unsigned int g_flags[16 * 32];         // per-group 8 flags, 128B apart

// ---------------- f32x2 helpers ----------------
__device__ __forceinline__ ull ffma2(ull a, ull b, ull c) {
    ull d;
    asm("fma.rn.f32x2 %0, %1, %2, %3;" : "=l"(d) : "l"(a), "l"(b), "l"(c));
    return d;
}
__device__ __forceinline__ ull pack2(float x) {
    ull d;
    asm("mov.b64 %0, {%1, %1};" : "=l"(d) : "f"(x));
    return d;
}
__device__ __forceinline__ ull packab(float a, float b) {
    ull d;
    asm("mov.b64 %0, {%1, %2};" : "=l"(d) : "f"(a), "f"(b));
    return d;
}
__device__ __forceinline__ float2 unpack2(ull v) {
    float2 r;
    asm("mov.b64 {%0, %1}, %2;" : "=f"(r.x), "=f"(r.y) : "l"(v));
    return r;
}
__device__ __forceinline__ unsigned umin4(uint4 v) {
    return min(min(v.x, v.y), min(v.z, v.w));
}

// =================================================================================
// Kernel 1: pre-projection GEMM (double-buffered smem)
// =================================================================================
__global__ __launch_bounds__(256, 2) void pre_gemm(
    const float* __restrict__ X,
    const float* __restrict__ Wf, const float* __restrict__ bf,
    const float* __restrict__ Wb, const float* __restrict__ bb)
{
    __shared__ float As[2][8][132];
    __shared__ float Bs[2][8][136];

    if (blockIdx.x == 0 && blockIdx.y == 0) {
        for (int i = threadIdx.x; i < 16 * 32; i += 256) g_flags[i] = 0u;
    }

    const int tid = threadIdx.x;
    const int m0 = blockIdx.y * 128;
    const int n0 = blockIdx.x * 128;
    const int dir = n0 >> 9;
    const int c0 = n0 & 511;
    const float* Bmat = dir ? Wb : Wf;
    const float* bias = dir ? bb : bf;

    const int ar  = tid >> 1;
    const int akq = (tid & 1) * 4;
    const int am  = m0 + ar;
    const float* Arow = X + ((size_t)(am & 31) * 512 + (size_t)(am >> 5)) * 512;

    const int bkk = tid >> 5;
    const int bnq = (tid & 31) * 4;

    const int ty = tid >> 4;
    const int tx = tid & 15;

    ull acc[4][8];
    #pragma unroll
    for (int i = 0; i < 4; ++i)
        #pragma unroll
        for (int j = 0; j < 8; ++j) acc[i][j] = 0ull;

    {
        float4 av = *(const float4*)(Arow + akq);
        float4 bv = *(const float4*)(Bmat + (size_t)bkk * 512 + c0 + bnq);
        As[0][akq + 0][ar] = av.x;
        As[0][akq + 1][ar] = av.y;
        As[0][akq + 2][ar] = av.z;
        As[0][akq + 3][ar] = av.w;
        *(float4*)&Bs[0][bkk][bnq] = bv;
    }
    __syncthreads();

    int buf = 0;
    for (int k0 = 0; k0 < 512; k0 += 8) {
        float4 av, bv;
        const bool more = (k0 + 8 < 512);
        if (more) {
            av = *(const float4*)(Arow + k0 + 8 + akq);
            bv = *(const float4*)(Bmat + (size_t)(k0 + 8 + bkk) * 512 + c0 + bnq);
        }

        #pragma unroll
        for (int k = 0; k < 8; ++k) {
            ulonglong2 a01 = *(const ulonglong2*)&As[buf][k][ty * 8];
            ulonglong2 a23 = *(const ulonglong2*)&As[buf][k][ty * 8 + 4];
            float4 bA = *(const float4*)&Bs[buf][k][tx * 8];
            float4 bB = *(const float4*)&Bs[buf][k][tx * 8 + 4];
            ull bd[8];
            bd[0] = pack2(bA.x); bd[1] = pack2(bA.y);
            bd[2] = pack2(bA.z); bd[3] = pack2(bA.w);
            bd[4] = pack2(bB.x); bd[5] = pack2(bB.y);
            bd[6] = pack2(bB.z); bd[7] = pack2(bB.w);
            #pragma unroll
            for (int j = 0; j < 8; ++j) {
                acc[0][j] = ffma2(a01.x, bd[j], acc[0][j]);
                acc[1][j] = ffma2(a01.y, bd[j], acc[1][j]);
                acc[2][j] = ffma2(a23.x, bd[j], acc[2][j]);
                acc[3][j] = ffma2(a23.y, bd[j], acc[3][j]);
            }
        }

        if (more) {
            int nb = buf ^ 1;
            As[nb][akq + 0][ar] = av.x;
            As[nb][akq + 1][ar] = av.y;
            As[nb][akq + 2][ar] = av.z;
            As[nb][akq + 3][ar] = av.w;
            *(float4*)&Bs[nb][bkk][bnq] = bv;
            __syncthreads();
            buf = nb;
        }
    }

    const int cg = c0 + tx * 8;
    float4 bl = *(const float4*)(bias + cg);
    float4 bh = *(const float4*)(bias + cg + 4);
    #pragma unroll
    for (int mp = 0; mp < 4; ++mp) {
        float2 v[8];
        #pragma unroll
        for (int j = 0; j < 8; ++j) v[j] = unpack2(acc[mp][j]);
        #pragma unroll
        for (int p = 0; p < 2; ++p) {
            int m = m0 + ty * 8 + mp * 2 + p;
            int tt = m >> 5, bb2 = m & 31;
            float* dst = g_pre + ((size_t)dir * 512 + tt) * 16384 + (size_t)bb2 * 512 + cg;
            float4 o0, o1;
            o0.x = (p ? v[0].y : v[0].x) + bl.x;
            o0.y = (p ? v[1].y : v[1].x) + bl.y;
            o0.z = (p ? v[2].y : v[2].x) + bl.z;
            o0.w = (p ? v[3].y : v[3].x) + bl.w;
            o1.x = (p ? v[4].y : v[4].x) + bh.x;
            o1.y = (p ? v[5].y : v[5].x) + bh.y;
            o1.z = (p ? v[6].y : v[6].x) + bh.z;
            o1.w = (p ? v[7].y : v[7].x) + bh.w;
            *(float4*)dst = o0;
            *(float4*)(dst + 4) = o1;
        }
    }
}

// =================================================================================
// Kernel 2: persistent bidirectional recurrence (v8)
//   128 CTAs = 2 dirs x 8 batch-groups(4) x 8 col-slices(64), 512 threads.
//   Thread = (c 0..63, ks 0..7): Wh[ks*64..+63][c0+c] in 32 f32x2 regs.
//   Barrier: per-CTA flag slots (8 u32 in one 32B sector per group).
//   Producers: st.release.gpu own slot. Consumers: ALL threads poll
//   ld.relaxed.v4 x2 + fence.acq_rel — no atomic serialization, no broadcast hop.
// =================================================================================
__global__ __launch_bounds__(512) void recur_kernel(
    const float* __restrict__ Wf, const float* __restrict__ Wb)
{
    __shared__ float s_h[4 * 520];      // [4 batches][512+8]
    __shared__ float s_red[8 * 256];    // [ks][b*64+c]

    const int tid = threadIdx.x;
    const int bx  = blockIdx.x;
    const int dir = bx & 1;
    const int grp = (bx >> 1) & 7;          // batch group 0..7 (4 batches)
    const int sl  = bx >> 4;                // col slice 0..7 (64 cols)
    const int c0  = sl * 64;
    const int bgl = grp * 4;
    const float* W = dir ? Wb : Wf;

    const int c  = tid & 63;
    const int ks = tid >> 6;

    // Wh column (c0+c), k in [ks*64, ks*64+64) -> 32 f32x2 regs
    ull wreg[16][2];
    #pragma unroll
    for (int j = 0; j < 16; ++j) {
        int k = ks * 64 + j * 4;
        const float* wp = W + (size_t)(512 + k) * 512 + c0 + c;
        wreg[j][0] = packab(wp[0],    wp[512]);
        wreg[j][1] = packab(wp[1024], wp[1536]);
    }

    // staging: 512 float4s, one per thread
    const int sb   = tid >> 7;              // batch row 0..3
    const int soff = (tid & 127) * 4;       // float offset in 512-row

    // reduce/store map (tid < 256): batch rb, col rc
    const int rb = tid >> 6;
    const int rc = tid & 63;

    unsigned int* fl = &g_flags[(dir * 8 + grp) * 32];

    // first step's pre-activation
    float pre = 0.f;
    {
        const int t0 = dir ? 511 : 0;
        if (tid < 256)
            pre = __ldcg(&g_pre[((size_t)dir * 512 + t0) * 16384 +
                                (size_t)(bgl + rb) * 512 + c0 + rc]);
    }

    for (int s = 0; s < 512; ++s) {
        const int t = dir ? (511 - s) : s;

        float hval = 0.f;
        if (s == 0) {
            if (tid < 256) hval = tanhf(pre);
        } else {
            // ---- all-thread poll: wait until all 8 group flags >= s ----
            const unsigned tgt = (unsigned)s;
            for (;;) {
                uint4 f0, f1;
                asm volatile("ld.relaxed.gpu.global.v4.u32 {%0,%1,%2,%3}, [%4];"
                             : "=r"(f0.x), "=r"(f0.y), "=r"(f0.z), "=r"(f0.w)
                             : "l"(fl) : "memory");
                asm volatile("ld.relaxed.gpu.global.v4.u32 {%0,%1,%2,%3}, [%4];"
                             : "=r"(f1.x), "=r"(f1.y), "=r"(f1.z), "=r"(f1.w)
                             : "l"(fl + 4) : "memory");
                if (min(umin4(f0), umin4(f1)) >= tgt) break;
            }
            asm volatile("fence.acq_rel.gpu;" ::: "memory");

            const int tp = dir ? (t + 1) : (t - 1);
            const float* hbase = g_hs + (size_t)tp * 32 * 1024 +
                                 (size_t)bgl * 1024 + dir * 512;

            // stage the group's 4 h rows (8KB) in one shot
            float4 v0 = __ldcg((const float4*)(hbase + sb * 1024 + soff));
            *(float4*)&s_h[sb * 520 + soff] = v0;
            __syncthreads();

            // mat-vec partials: smem reads warp-broadcast (address = f(b,ks) only)
            ull acc[4] = {0ull, 0ull, 0ull, 0ull};
            #pragma unroll
            for (int b = 0; b < 4; ++b) {
                const ulonglong2* hp = (const ulonglong2*)&s_h[b * 520 + ks * 64];
                #pragma unroll
                for (int j = 0; j < 16; ++j) {
                    ulonglong2 h2 = hp[j];
                    acc[b] = ffma2(h2.x, wreg[j][0], acc[b]);
                    acc[b] = ffma2(h2.y, wreg[j][1], acc[b]);
                }
            }
            #pragma unroll
            for (int b = 0; b < 4; ++b) {
                float2 p = unpack2(acc[b]);
                s_red[ks * 256 + b * 64 + c] = p.x + p.y;
            }
            __syncthreads();

            if (tid < 256) {
                float sum = pre;
                #pragma unroll
                for (int k8 = 0; k8 < 8; ++k8) sum += s_red[k8 * 256 + tid];
                hval = tanhf(sum);
            }
        }

        if (tid < 256)
            __stcg(&g_hs[((size_t)t * 32 + bgl + rb) * 1024 +
                         dir * 512 + c0 + rc], hval);

        if (s < 511) {
            __syncthreads();   // all h stores of this CTA before the flag release
            if (tid == 0)
                asm volatile("st.release.gpu.global.u32 [%0], %1;"
                             :: "l"(fl + sl), "r"((unsigned)(s + 1)) : "memory");
            // prefetch next step's pre (independent of the next poll)
            const int tn = dir ? (510 - s) : (s + 1);
            if (tid < 256)
                pre = __ldcg(&g_pre[((size_t)dir * 512 + tn) * 16384 +
                                    (size_t)(bgl + rb) * 512 + c0 + rc]);
        }
    }
}

// =================================================================================
// Kernel 3: output GEMM (double-buffered smem)
// =================================================================================
__global__ __launch_bounds__(256, 2) void out_gemm(
    const float* __restrict__ Wo, const float* __restrict__ bo,
    float* __restrict__ out)
{
    __shared__ float As[2][8][132];
    __shared__ float Bs[2][8][136];

    const int tid = threadIdx.x;
    const int m0 = blockIdx.y * 128;
    const int n0 = blockIdx.x * 128;

    const int ar  = tid >> 1;
    const int akq = (tid & 1) * 4;
    const float* Arow = g_hs + (size_t)(m0 + ar) * 1024;

    const int bkk = tid >> 5;
    const int bnq = (tid & 31) * 4;

    const int ty = tid >> 4;
    const int tx = tid & 15;

    ull acc[4][8];
    #pragma unroll
    for (int i = 0; i < 4; ++i)
        #pragma unroll
        for (int j = 0; j < 8; ++j) acc[i][j] = 0ull;

    {
        float4 av = *(const float4*)(Arow + akq);
        float4 bv = *(const float4*)(Wo + (size_t)bkk * 512 + n0 + bnq);
        As[0][akq + 0][ar] = av.x;
        As[0][akq + 1][ar] = av.y;
        As[0][akq + 2][ar] = av.z;
        As[0][akq + 3][ar] = av.w;
        *(float4*)&Bs[0][bkk][bnq] = bv;
    }
    __syncthreads();

    int buf = 0;
    for (int k0 = 0; k0 < 1024; k0 += 8) {
        float4 av, bv;
        const bool more = (k0 + 8 < 1024);
        if (more) {
            av = *(const float4*)(Arow + k0 + 8 + akq);
            bv = *(const float4*)(Wo + (size_t)(k0 + 8 + bkk) * 512 + n0 + bnq);
        }

        #pragma unroll
        for (int k = 0; k < 8; ++k) {
            ulonglong2 a01 = *(const ulonglong2*)&As[buf][k][ty * 8];
            ulonglong2 a23 = *(const ulonglong2*)&As[buf][k][ty * 8 + 4];
            float4 bA = *(const float4*)&Bs[buf][k][tx * 8];
            float4 bB = *(const float4*)&Bs[buf][k][tx * 8 + 4];
            ull bd[8];
            bd[0] = pack2(bA.x); bd[1] = pack2(bA.y);
            bd[2] = pack2(bA.z); bd[3] = pack2(bA.w);
            bd[4] = pack2(bB.x); bd[5] = pack2(bB.y);
            bd[6] = pack2(bB.z); bd[7] = pack2(bB.w);
            #pragma unroll
            for (int j = 0; j < 8; ++j) {
                acc[0][j] = ffma2(a01.x, bd[j], acc[0][j]);
                acc[1][j] = ffma2(a01.y, bd[j], acc[1][j]);
                acc[2][j] = ffma2(a23.x, bd[j], acc[2][j]);
                acc[3][j] = ffma2(a23.y, bd[j], acc[3][j]);
            }
        }

        if (more) {
            int nb = buf ^ 1;
            As[nb][akq + 0][ar] = av.x;
            As[nb][akq + 1][ar] = av.y;
            As[nb][akq + 2][ar] = av.z;
            As[nb][akq + 3][ar] = av.w;
            *(float4*)&Bs[nb][bkk][bnq] = bv;
            __syncthreads();
            buf = nb;
        }
    }

    const int og = n0 + tx * 8;
    float4 bl = *(const float4*)(bo + og);
    float4 bh = *(const float4*)(bo + og + 4);
    #pragma unroll
    for (int mp = 0; mp < 4; ++mp) {
        float2 v[8];
        #pragma unroll
        for (int j = 0; j < 8; ++j) v[j] = unpack2(acc[mp][j]);
        #pragma unroll
        for (int p = 0; p < 2; ++p) {
            int m = m0 + ty * 8 + mp * 2 + p;
            int tt = m >> 5, bb2 = m & 31;
            float* dst = out + ((size_t)bb2 * 512 + tt) * 512 + og;
            float4 o0, o1;
            o0.x = (p ? v[0].y : v[0].x) + bl.x;
            o0.y = (p ? v[1].y : v[1].x) + bl.y;
            o0.z = (p ? v[2].y : v[2].x) + bl.z;
            o0.w = (p ? v[3].y : v[3].x) + bl.w;
            o1.x = (p ? v[4].y : v[4].x) + bh.x;
            o1.y = (p ? v[5].y : v[5].x) + bh.y;
            o1.z = (p ? v[6].y : v[6].x) + bh.z;
            o1.w = (p ? v[7].y : v[7].x) + bh.w;
            *(float4*)dst = o0;
            *(float4*)(dst + 4) = o1;
        }
    }
}

// =================================================================================
extern "C" void kernel_launch(void* const* d_in, const int* in_sizes, int n_in,
                              void* d_out, int out_size)
{
    const float* X  = (const float*)d_in[0];
    const float* Wf = (const float*)d_in[1];
    const float* bf = (const float*)d_in[2];
    const float* Wb = (const float*)d_in[3];
    const float* bb = (const float*)d_in[4];
    const float* Wo = (const float*)d_in[5];
    const float* bo = (const float*)d_in[6];
    float* out = (float*)d_out;

    pre_gemm<<<dim3(8, 128), 256>>>(X, Wf, bf, Wb, bb);
    recur_kernel<<<128, 512>>>(Wf, Wb);
    out_gemm<<<dim3(4, 128), 256>>>(Wo, bo, out);
}

// round 9
// speedup vs baseline: 1.2491x; 1.2092x over previous
#include <cuda_runtime.h>
#include <cuda_bf16.h>
#include <math.h>
#include <stdint.h>

typedef unsigned long long ull;

// ---------------- scratch (static device globals; no allocation) ----------------
__device__ float g_pre[2u * 512u * 32u * 512u];   // [dir][t][b][c] 64MB
__device__ float g_hs[512u * 32u * 1024u];        // [t][b][dir*512+c] 64MB
__device__ unsigned int g_flags[16 * 32];         // per-(dir,grp): 8 slice flags, 128B apart

// ---------------- f32x2 helpers ----------------
__device__ __forceinline__ ull ffma2(ull a, ull b, ull c) {
    ull d;
    asm("fma.rn.f32x2 %0, %1, %2, %3;" : "=l"(d) : "l"(a), "l"(b), "l"(c));
    return d;
}
__device__ __forceinline__ ull pack2(float x) {
    ull d;
    asm("mov.b64 %0, {%1, %1};" : "=l"(d) : "f"(x));
    return d;
}
__device__ __forceinline__ ull packab(float a, float b) {
    ull d;
    asm("mov.b64 %0, {%1, %2};" : "=l"(d) : "f"(a), "f"(b));
    return d;
}
__device__ __forceinline__ float2 unpack2(ull v) {
    float2 r;
    asm("mov.b64 {%0, %1}, %2;" : "=f"(r.x), "=f"(r.y) : "l"(v));
    return r;
}

// =================================================================================
// Kernel 1: pre-projection GEMM (double-buffered smem)
// =================================================================================
__global__ __launch_bounds__(256, 2) void pre_gemm(
    const float* __restrict__ X,
    const float* __restrict__ Wf, const float* __restrict__ bf,
    const float* __restrict__ Wb, const float* __restrict__ bb)
{
    __shared__ float As[2][8][132];
    __shared__ float Bs[2][8][136];

    if (blockIdx.x == 0 && blockIdx.y == 0) {
        for (int i = threadIdx.x; i < 16 * 32; i += 256) g_flags[i] = 0u;
    }

    const int tid = threadIdx.x;
    const int m0 = blockIdx.y * 128;
    const int n0 = blockIdx.x * 128;
    const int dir = n0 >> 9;
    const int c0 = n0 & 511;
    const float* Bmat = dir ? Wb : Wf;
    const float* bias = dir ? bb : bf;

    const int ar  = tid >> 1;
    const int akq = (tid & 1) * 4;
    const int am  = m0 + ar;
    const float* Arow = X + ((size_t)(am & 31) * 512 + (size_t)(am >> 5)) * 512;

    const int bkk = tid >> 5;
    const int bnq = (tid & 31) * 4;

    const int ty = tid >> 4;
    const int tx = tid & 15;

    ull acc[4][8];
    #pragma unroll
    for (int i = 0; i < 4; ++i)
        #pragma unroll
        for (int j = 0; j < 8; ++j) acc[i][j] = 0ull;

    {
        float4 av = *(const float4*)(Arow + akq);
        float4 bv = *(const float4*)(Bmat + (size_t)bkk * 512 + c0 + bnq);
        As[0][akq + 0][ar] = av.x;
        As[0][akq + 1][ar] = av.y;
        As[0][akq + 2][ar] = av.z;
        As[0][akq + 3][ar] = av.w;
        *(float4*)&Bs[0][bkk][bnq] = bv;
    }
    __syncthreads();

    int buf = 0;
    for (int k0 = 0; k0 < 512; k0 += 8) {
        float4 av, bv;
        const bool more = (k0 + 8 < 512);
        if (more) {
            av = *(const float4*)(Arow + k0 + 8 + akq);
            bv = *(const float4*)(Bmat + (size_t)(k0 + 8 + bkk) * 512 + c0 + bnq);
        }

        #pragma unroll
        for (int k = 0; k < 8; ++k) {
            ulonglong2 a01 = *(const ulonglong2*)&As[buf][k][ty * 8];
            ulonglong2 a23 = *(const ulonglong2*)&As[buf][k][ty * 8 + 4];
            float4 bA = *(const float4*)&Bs[buf][k][tx * 8];
            float4 bB = *(const float4*)&Bs[buf][k][tx * 8 + 4];
            ull bd[8];
            bd[0] = pack2(bA.x); bd[1] = pack2(bA.y);
            bd[2] = pack2(bA.z); bd[3] = pack2(bA.w);
            bd[4] = pack2(bB.x); bd[5] = pack2(bB.y);
            bd[6] = pack2(bB.z); bd[7] = pack2(bB.w);
            #pragma unroll
            for (int j = 0; j < 8; ++j) {
                acc[0][j] = ffma2(a01.x, bd[j], acc[0][j]);
                acc[1][j] = ffma2(a01.y, bd[j], acc[1][j]);
                acc[2][j] = ffma2(a23.x, bd[j], acc[2][j]);
                acc[3][j] = ffma2(a23.y, bd[j], acc[3][j]);
            }
        }

        if (more) {
            int nb = buf ^ 1;
            As[nb][akq + 0][ar] = av.x;
            As[nb][akq + 1][ar] = av.y;
            As[nb][akq + 2][ar] = av.z;
            As[nb][akq + 3][ar] = av.w;
            *(float4*)&Bs[nb][bkk][bnq] = bv;
            __syncthreads();
            buf = nb;
        }
    }

    const int cg = c0 + tx * 8;
    float4 bl = *(const float4*)(bias + cg);
    float4 bh = *(const float4*)(bias + cg + 4);
    #pragma unroll
    for (int mp = 0; mp < 4; ++mp) {
        float2 v[8];
        #pragma unroll
        for (int j = 0; j < 8; ++j) v[j] = unpack2(acc[mp][j]);
        #pragma unroll
        for (int p = 0; p < 2; ++p) {
            int m = m0 + ty * 8 + mp * 2 + p;
            int tt = m >> 5, bb2 = m & 31;
            float* dst = g_pre + ((size_t)dir * 512 + tt) * 16384 + (size_t)bb2 * 512 + cg;
            float4 o0, o1;
            o0.x = (p ? v[0].y : v[0].x) + bl.x;
            o0.y = (p ? v[1].y : v[1].x) + bl.y;
            o0.z = (p ? v[2].y : v[2].x) + bl.z;
            o0.w = (p ? v[3].y : v[3].x) + bl.w;
            o1.x = (p ? v[4].y : v[4].x) + bh.x;
            o1.y = (p ? v[5].y : v[5].x) + bh.y;
            o1.z = (p ? v[6].y : v[6].x) + bh.z;
            o1.w = (p ? v[7].y : v[7].x) + bh.w;
            *(float4*)dst = o0;
            *(float4*)(dst + 4) = o1;
        }
    }
}

// =================================================================================
// Kernel 2: persistent bidirectional recurrence (v9 — per-slice dataflow)
//   128 CTAs = 2 dirs x 8 batch-groups(4) x 8 col-slices(64), 512 threads.
//   Thread (c 0..63, ks 0..7) consumes h ONLY from producer-slice ks:
//   each ks-group (2 warps) waits on flag[ks] alone (ld.acquire poll), loads its
//   1KB slice, named-bar 64, computes its partials — groups proceed in slice
//   arrival order, overlapping wait latency with other groups' compute.
//   CTA-wide sync only at reduce + before the release.
// =================================================================================
__global__ __launch_bounds__(512) void recur_kernel(
    const float* __restrict__ Wf, const float* __restrict__ Wb)
{
    __shared__ float s_h[4 * 520];      // [4 batches][512+8]
    __shared__ float s_red[8 * 256];    // [ks][b*64+c]

    const int tid = threadIdx.x;
    const int bx  = blockIdx.x;
    const int dir = bx & 1;
    const int grp = (bx >> 1) & 7;          // batch group 0..7 (4 batches)
    const int sl  = bx >> 4;                // col slice 0..7 (64 cols)
    const int c0  = sl * 64;
    const int bgl = grp * 4;
    const float* W = dir ? Wb : Wf;

    const int c  = tid & 63;
    const int ks = tid >> 6;

    // Wh column (c0+c), k in [ks*64, ks*64+64) -> 32 f32x2 regs
    ull wreg[16][2];
    #pragma unroll
    for (int j = 0; j < 16; ++j) {
        int k = ks * 64 + j * 4;
        const float* wp = W + (size_t)(512 + k) * 512 + c0 + c;
        wreg[j][0] = packab(wp[0],    wp[512]);
        wreg[j][1] = packab(wp[1024], wp[1536]);
    }

    // slice-load map within the ks-group: lane c -> batch lb, float offset lo
    const int lb = c >> 4;                  // 0..3
    const int lo = (c & 15) * 4;            // 0..60

    // reduce/store map (tid < 256): batch rb, col rc
    const int rb = tid >> 6;
    const int rc = tid & 63;

    unsigned int* fl = &g_flags[(dir * 8 + grp) * 32];

    // first step's pre-activation
    float pre = 0.f;
    {
        const int t0 = dir ? 511 : 0;
        if (tid < 256)
            pre = __ldcg(&g_pre[((size_t)dir * 512 + t0) * 16384 +
                                (size_t)(bgl + rb) * 512 + c0 + rc]);
    }

    for (int s = 0; s < 512; ++s) {
        const int t = dir ? (511 - s) : s;

        float hval = 0.f;
        if (s == 0) {
            if (tid < 256) hval = tanhf(pre);
        } else {
            // ---- per-slice wait: this ks-group needs only producer slice ks ----
            {
                const unsigned tgt = (unsigned)s;
                unsigned v;
                do {
                    asm volatile("ld.acquire.gpu.global.u32 %0, [%1];"
                                 : "=r"(v) : "l"(fl + ks) : "memory");
                } while (v < tgt);
            }

            // load this group's 1KB slice: h[tp][bgl+lb][dir*512 + ks*64 + lo..+3]
            const int tp = dir ? (t + 1) : (t - 1);
            {
                const float* hp = g_hs + ((size_t)tp * 32 + bgl + lb) * 1024 +
                                  dir * 512 + ks * 64 + lo;
                float4 v4 = __ldcg((const float4*)hp);
                *(float4*)&s_h[lb * 520 + ks * 64 + lo] = v4;
            }
            // sync the 2 warps of this ks-group only (warps 2*ks, 2*ks+1)
            asm volatile("bar.sync %0, 64;" :: "r"(ks + 1) : "memory");

            // partials for this k-range (smem reads warp-broadcast)
            ull acc[4] = {0ull, 0ull, 0ull, 0ull};
            #pragma unroll
            for (int b = 0; b < 4; ++b) {
                const ulonglong2* hp = (const ulonglong2*)&s_h[b * 520 + ks * 64];
                #pragma unroll
                for (int j = 0; j < 16; ++j) {
                    ulonglong2 h2 = hp[j];
                    acc[b] = ffma2(h2.x, wreg[j][0], acc[b]);
                    acc[b] = ffma2(h2.y, wreg[j][1], acc[b]);
                }
            }
            #pragma unroll
            for (int b = 0; b < 4; ++b) {
                float2 p = unpack2(acc[b]);
                s_red[ks * 256 + b * 64 + c] = p.x + p.y;
            }
            __syncthreads();

            if (tid < 256) {
                float sum = pre;
                #pragma unroll
                for (int k8 = 0; k8 < 8; ++k8) sum += s_red[k8 * 256 + tid];
                hval = tanhf(sum);
            }
        }

        if (tid < 256)
            __stcg(&g_hs[((size_t)t * 32 + bgl + rb) * 1024 +
                         dir * 512 + c0 + rc], hval);

        if (s < 511) {
            __syncthreads();   // all h stores of this CTA before the flag release
            if (tid == 0)
                asm volatile("st.release.gpu.global.u32 [%0], %1;"
                             :: "l"(fl + sl), "r"((unsigned)(s + 1)) : "memory");
            // prefetch next step's pre (independent of the next polls)
            const int tn = dir ? (510 - s) : (s + 1);
            if (tid < 256)
                pre = __ldcg(&g_pre[((size_t)dir * 512 + tn) * 16384 +
                                    (size_t)(bgl + rb) * 512 + c0 + rc]);
        }
    }
}

// =================================================================================
// Kernel 3: output GEMM (double-buffered smem)
// =================================================================================
__global__ __launch_bounds__(256, 2) void out_gemm(
    const float* __restrict__ Wo, const float* __restrict__ bo,
    float* __restrict__ out)
{
    __shared__ float As[2][8][132];
    __shared__ float Bs[2][8][136];

    const int tid = threadIdx.x;
    const int m0 = blockIdx.y * 128;
    const int n0 = blockIdx.x * 128;

    const int ar  = tid >> 1;
    const int akq = (tid & 1) * 4;
    const float* Arow = g_hs + (size_t)(m0 + ar) * 1024;

    const int bkk = tid >> 5;
    const int bnq = (tid & 31) * 4;

    const int ty = tid >> 4;
    const int tx = tid & 15;

    ull acc[4][8];
    #pragma unroll
    for (int i = 0; i < 4; ++i)
        #pragma unroll
        for (int j = 0; j < 8; ++j) acc[i][j] = 0ull;

    {
        float4 av = *(const float4*)(Arow + akq);
        float4 bv = *(const float4*)(Wo + (size_t)bkk * 512 + n0 + bnq);
        As[0][akq + 0][ar] = av.x;
        As[0][akq + 1][ar] = av.y;
        As[0][akq + 2][ar] = av.z;
        As[0][akq + 3][ar] = av.w;
        *(float4*)&Bs[0][bkk][bnq] = bv;
    }
    __syncthreads();

    int buf = 0;
    for (int k0 = 0; k0 < 1024; k0 += 8) {
        float4 av, bv;
        const bool more = (k0 + 8 < 1024);
        if (more) {
            av = *(const float4*)(Arow + k0 + 8 + akq);
            bv = *(const float4*)(Wo + (size_t)(k0 + 8 + bkk) * 512 + n0 + bnq);
        }

        #pragma unroll
        for (int k = 0; k < 8; ++k) {
            ulonglong2 a01 = *(const ulonglong2*)&As[buf][k][ty * 8];
            ulonglong2 a23 = *(const ulonglong2*)&As[buf][k][ty * 8 + 4];
            float4 bA = *(const float4*)&Bs[buf][k][tx * 8];
            float4 bB = *(const float4*)&Bs[buf][k][tx * 8 + 4];
            ull bd[8];
            bd[0] = pack2(bA.x); bd[1] = pack2(bA.y);
            bd[2] = pack2(bA.z); bd[3] = pack2(bA.w);
            bd[4] = pack2(bB.x); bd[5] = pack2(bB.y);
            bd[6] = pack2(bB.z); bd[7] = pack2(bB.w);
            #pragma unroll
            for (int j = 0; j < 8; ++j) {
                acc[0][j] = ffma2(a01.x, bd[j], acc[0][j]);
                acc[1][j] = ffma2(a01.y, bd[j], acc[1][j]);
                acc[2][j] = ffma2(a23.x, bd[j], acc[2][j]);
                acc[3][j] = ffma2(a23.y, bd[j], acc[3][j]);
            }
        }

        if (more) {
            int nb = buf ^ 1;
            As[nb][akq + 0][ar] = av.x;
            As[nb][akq + 1][ar] = av.y;
            As[nb][akq + 2][ar] = av.z;
            As[nb][akq + 3][ar] = av.w;
            *(float4*)&Bs[nb][bkk][bnq] = bv;
            __syncthreads();
            buf = nb;
        }
    }

    const int og = n0 + tx * 8;
    float4 bl = *(const float4*)(bo + og);
    float4 bh = *(const float4*)(bo + og + 4);
    #pragma unroll
    for (int mp = 0; mp < 4; ++mp) {
        float2 v[8];
        #pragma unroll
        for (int j = 0; j < 8; ++j) v[j] = unpack2(acc[mp][j]);
        #pragma unroll
        for (int p = 0; p < 2; ++p) {
            int m = m0 + ty * 8 + mp * 2 + p;
            int tt = m >> 5, bb2 = m & 31;
            float* dst = out + ((size_t)bb2 * 512 + tt) * 512 + og;
            float4 o0, o1;
            o0.x = (p ? v[0].y : v[0].x) + bl.x;
            o0.y = (p ? v[1].y : v[1].x) + bl.y;
            o0.z = (p ? v[2].y : v[2].x) + bl.z;
            o0.w = (p ? v[3].y : v[3].x) + bl.w;
            o1.x = (p ? v[4].y : v[4].x) + bh.x;
            o1.y = (p ? v[5].y : v[5].x) + bh.y;
            o1.z = (p ? v[6].y : v[6].x) + bh.z;
            o1.w = (p ? v[7].y : v[7].x) + bh.w;
            *(float4*)dst = o0;
            *(float4*)(dst + 4) = o1;
        }
    }
}

// =================================================================================
extern "C" void kernel_launch(void* const* d_in, const int* in_sizes, int n_in,
                              void* d_out, int out_size)
{
    const float* X  = (const float*)d_in[0];
    const float* Wf = (const float*)d_in[1];
    const float* bf = (const float*)d_in[2];
    const float* Wb = (const float*)d_in[3];
    const float* bb = (const float*)d_in[4];
    const float* Wo = (const float*)d_in[5];
    const float* bo = (const float*)d_in[6];
    float* out = (float*)d_out;

    pre_gemm<<<dim3(8, 128), 256>>>(X, Wf, bf, Wb, bb);
    recur_kernel<<<128, 512>>>(Wf, Wb);
    out_gemm<<<dim3(4, 128), 256>>>(Wo, bo, out);
}

// round 10
// speedup vs baseline: 1.2972x; 1.0385x over previous
#include <cuda_runtime.h>
#include <cuda_bf16.h>
#include <math.h>
#include <stdint.h>

typedef unsigned long long ull;

// ---------------- scratch (static device globals; no allocation) ----------------
__device__ float g_pre[2u * 512u * 32u * 512u];   // [dir][t][b][c] 64MB
__device__ float g_hs[512u * 32u * 1024u];        // [t][b][dir*512+c] 64MB
__device__ unsigned int g_bar[16 * 32];           // per-(dir,grp) counters, 128B apart

// ---------------- f32x2 helpers ----------------
__device__ __forceinline__ ull ffma2(ull a, ull b, ull c) {
    ull d;
    asm("fma.rn.f32x2 %0, %1, %2, %3;" : "=l"(d) : "l"(a), "l"(b), "l"(c));
    return d;
}
__device__ __forceinline__ ull pack2(float x) {
    ull d;
    asm("mov.b64 %0, {%1, %1};" : "=l"(d) : "f"(x));
    return d;
}
__device__ __forceinline__ ull packab(float a, float b) {
    ull d;
    asm("mov.b64 %0, {%1, %2};" : "=l"(d) : "f"(a), "f"(b));
    return d;
}
__device__ __forceinline__ float2 unpack2(ull v) {
    float2 r;
    asm("mov.b64 {%0, %1}, %2;" : "=f"(r.x), "=f"(r.y) : "l"(v));
    return r;
}

// duplicated-B smem slot for column n in [0,128):
// group stride 17 ulls (odd) -> writer's 4 stores hit distinct banks,
// reader (slot j*17+tx, tx 0..15) is 128B-contiguous, 1 wavefront, broadcast
// across the two ty-halves of the warp.
__device__ __forceinline__ int bslot(int n) { return (n & 7) * 17 + (n >> 3); }

// =================================================================================
// Kernel 1: pre-projection GEMM (double-buffered, duplicated-B smem, bank-fixed)
// =================================================================================
__global__ __launch_bounds__(256, 2) void pre_gemm(
    const float* __restrict__ X,
    const float* __restrict__ Wf, const float* __restrict__ bf,
    const float* __restrict__ Wb, const float* __restrict__ bb)
{
    __shared__ float As[2][8][132];
    __shared__ ull   Bsd[2][8][136];   // 8 groups x 17 ulls per k-row

    if (blockIdx.x == 0 && blockIdx.y == 0 && threadIdx.x < 16)
        g_bar[threadIdx.x * 32] = 0u;

    const int tid = threadIdx.x;
    const int m0 = blockIdx.y * 128;
    const int n0 = blockIdx.x * 128;
    const int dir = n0 >> 9;
    const int c0 = n0 & 511;
    const float* Bmat = dir ? Wb : Wf;
    const float* bias = dir ? bb : bf;

    const int ar  = tid >> 1;
    const int akq = (tid & 1) * 4;
    const int am  = m0 + ar;
    const float* Arow = X + ((size_t)(am & 31) * 512 + (size_t)(am >> 5)) * 512;

    const int bkk = tid >> 5;
    const int bnq = (tid & 31) * 4;

    const int ty = tid >> 4;
    const int tx = tid & 15;

    ull acc[4][8];
    #pragma unroll
    for (int i = 0; i < 4; ++i)
        #pragma unroll
        for (int j = 0; j < 8; ++j) acc[i][j] = 0ull;

    // prologue: fill buffer 0
    {
        float4 av = *(const float4*)(Arow + akq);
        float4 bv = *(const float4*)(Bmat + (size_t)bkk * 512 + c0 + bnq);
        As[0][akq + 0][ar] = av.x;
        As[0][akq + 1][ar] = av.y;
        As[0][akq + 2][ar] = av.z;
        As[0][akq + 3][ar] = av.w;
        Bsd[0][bkk][bslot(bnq + 0)] = pack2(bv.x);
        Bsd[0][bkk][bslot(bnq + 1)] = pack2(bv.y);
        Bsd[0][bkk][bslot(bnq + 2)] = pack2(bv.z);
        Bsd[0][bkk][bslot(bnq + 3)] = pack2(bv.w);
    }
    __syncthreads();

    int buf = 0;
    for (int k0 = 0; k0 < 512; k0 += 8) {
        float4 av, bv;
        const bool more = (k0 + 8 < 512);
        if (more) {
            av = *(const float4*)(Arow + k0 + 8 + akq);
            bv = *(const float4*)(Bmat + (size_t)(k0 + 8 + bkk) * 512 + c0 + bnq);
        }

        #pragma unroll
        for (int k = 0; k < 8; ++k) {
            ulonglong2 a01 = *(const ulonglong2*)&As[buf][k][ty * 8];
            ulonglong2 a23 = *(const ulonglong2*)&As[buf][k][ty * 8 + 4];
            ull bd[8];
            #pragma unroll
            for (int j = 0; j < 8; ++j) bd[j] = Bsd[buf][k][j * 17 + tx];
            #pragma unroll
            for (int j = 0; j < 8; ++j) {
                acc[0][j] = ffma2(a01.x, bd[j], acc[0][j]);
                acc[1][j] = ffma2(a01.y, bd[j], acc[1][j]);
                acc[2][j] = ffma2(a23.x, bd[j], acc[2][j]);
                acc[3][j] = ffma2(a23.y, bd[j], acc[3][j]);
            }
        }

        if (more) {
            int nb = buf ^ 1;
            As[nb][akq + 0][ar] = av.x;
            As[nb][akq + 1][ar] = av.y;
            As[nb][akq + 2][ar] = av.z;
            As[nb][akq + 3][ar] = av.w;
            Bsd[nb][bkk][bslot(bnq + 0)] = pack2(bv.x);
            Bsd[nb][bkk][bslot(bnq + 1)] = pack2(bv.y);
            Bsd[nb][bkk][bslot(bnq + 2)] = pack2(bv.z);
            Bsd[nb][bkk][bslot(bnq + 3)] = pack2(bv.w);
            __syncthreads();
            buf = nb;
        }
    }

    // micro-tile column j maps to global col tx*8+j (matches bslot layout)
    const int cg = c0 + tx * 8;
    float4 bl = *(const float4*)(bias + cg);
    float4 bh = *(const float4*)(bias + cg + 4);
    #pragma unroll
    for (int mp = 0; mp < 4; ++mp) {
        float2 v[8];
        #pragma unroll
        for (int j = 0; j < 8; ++j) v[j] = unpack2(acc[mp][j]);
        #pragma unroll
        for (int p = 0; p < 2; ++p) {
            int m = m0 + ty * 8 + mp * 2 + p;
            int tt = m >> 5, bb2 = m & 31;
            float* dst = g_pre + ((size_t)dir * 512 + tt) * 16384 + (size_t)bb2 * 512 + cg;
            float4 o0, o1;
            o0.x = (p ? v[0].y : v[0].x) + bl.x;
            o0.y = (p ? v[1].y : v[1].x) + bl.y;
            o0.z = (p ? v[2].y : v[2].x) + bl.z;
            o0.w = (p ? v[3].y : v[3].x) + bl.w;
            o1.x = (p ? v[4].y : v[4].x) + bh.x;
            o1.y = (p ? v[5].y : v[5].x) + bh.y;
            o1.z = (p ? v[6].y : v[6].x) + bh.z;
            o1.w = (p ? v[7].y : v[7].x) + bh.w;
            *(float4*)dst = o0;
            *(float4*)(dst + 4) = o1;
        }
    }
}

// =================================================================================
// Kernel 2: persistent bidirectional recurrence (R6 v6 — verbatim, measured best)
//   128 CTAs = 2 dirs x 8 batch-groups(4) x 8 col-slices(64), 512 threads.
//   Thread = (c 0..63, ks 0..7): Wh[ks*64..+63][c0+c] in 32 f32x2 regs.
//   8-CTA software barrier: padded counter, red.release + thread0 acquire-poll,
//   next pre prefetched under the barrier.
// =================================================================================
__global__ __launch_bounds__(512) void recur_kernel(
    const float* __restrict__ Wf, const float* __restrict__ Wb)
{
    __shared__ float s_h[4 * 520];      // [4 batches][512+8]
    __shared__ float s_red[8 * 256];    // [ks][b*64+c]

    const int tid = threadIdx.x;
    const int bx  = blockIdx.x;
    const int dir = bx & 1;
    const int grp = (bx >> 1) & 7;          // batch group 0..7 (4 batches)
    const int sl  = bx >> 4;                // col slice 0..7 (64 cols)
    const int c0  = sl * 64;
    const int bgl = grp * 4;
    const float* W = dir ? Wb : Wf;

    const int c  = tid & 63;
    const int ks = tid >> 6;

    // Wh column (c0+c), k in [ks*64, ks*64+64) -> 32 f32x2 regs
    ull wreg[16][2];
    #pragma unroll
    for (int j = 0; j < 16; ++j) {
        int k = ks * 64 + j * 4;
        const float* wp = W + (size_t)(512 + k) * 512 + c0 + c;
        wreg[j][0] = packab(wp[0],    wp[512]);
        wreg[j][1] = packab(wp[1024], wp[1536]);
    }

    // staging: 512 float4s, one per thread
    const int sb   = tid >> 7;              // batch row 0..3
    const int soff = (tid & 127) * 4;       // float offset in 512-row

    // reduce/store map (tid < 256): batch rb, col rc
    const int rb = tid >> 6;
    const int rc = tid & 63;

    unsigned int* bar = &g_bar[(dir * 8 + grp) * 32];

    // first step's pre-activation
    float pre = 0.f;
    {
        const int t0 = dir ? 511 : 0;
        if (tid < 256)
            pre = __ldcg(&g_pre[((size_t)dir * 512 + t0) * 16384 +
                                (size_t)(bgl + rb) * 512 + c0 + rc]);
    }

    for (int s = 0; s < 512; ++s) {
        const int t = dir ? (511 - s) : s;

        float hval = 0.f;
        if (s == 0) {
            if (tid < 256) hval = tanhf(pre);
        } else {
            const int tp = dir ? (t + 1) : (t - 1);
            const float* hbase = g_hs + (size_t)tp * 32 * 1024 +
                                 (size_t)bgl * 1024 + dir * 512;

            // stage the group's 4 h rows (8KB) in one shot
            float4 v0 = __ldcg((const float4*)(hbase + sb * 1024 + soff));
            *(float4*)&s_h[sb * 520 + soff] = v0;
            __syncthreads();

            // mat-vec partials: smem reads warp-broadcast (address = f(b,ks) only)
            ull acc[4] = {0ull, 0ull, 0ull, 0ull};
            #pragma unroll
            for (int b = 0; b < 4; ++b) {
                const ulonglong2* hp = (const ulonglong2*)&s_h[b * 520 + ks * 64];
                #pragma unroll
                for (int j = 0; j < 16; ++j) {
                    ulonglong2 h2 = hp[j];
                    acc[b] = ffma2(h2.x, wreg[j][0], acc[b]);
                    acc[b] = ffma2(h2.y, wreg[j][1], acc[b]);
                }
            }
            #pragma unroll
            for (int b = 0; b < 4; ++b) {
                float2 p = unpack2(acc[b]);
                s_red[ks * 256 + b * 64 + c] = p.x + p.y;
            }
            __syncthreads();

            if (tid < 256) {
                float sum = pre;
                #pragma unroll
                for (int k8 = 0; k8 < 8; ++k8) sum += s_red[k8 * 256 + tid];
                hval = tanhf(sum);
            }
        }

        if (tid < 256)
            __stcg(&g_hs[((size_t)t * 32 + bgl + rb) * 1024 +
                         dir * 512 + c0 + rc], hval);

        if (s < 511) {
            __syncthreads();   // CTA-HB: all h stores ordered before thread0's release
            if (tid == 0)
                asm volatile("red.release.gpu.global.add.u32 [%0], 1;"
                             :: "l"(bar) : "memory");
            // prefetch next step's pre under the barrier
            const int tn = dir ? (510 - s) : (s + 1);
            float npre = 0.f;
            if (tid < 256)
                npre = __ldcg(&g_pre[((size_t)dir * 512 + tn) * 16384 +
                                     (size_t)(bgl + rb) * 512 + c0 + rc]);
            if (tid == 0) {
                const unsigned target = (unsigned)(s + 1) * 8u;
                unsigned v;
                for (;;) {
                    asm volatile("ld.acquire.gpu.global.u32 %0, [%1];"
                                 : "=r"(v) : "l"(bar) : "memory");
                    if (v >= target) break;
                }
            }
            __syncthreads();
            pre = npre;
        }
    }
}

// =================================================================================
// Kernel 3: output GEMM (double-buffered, duplicated-B smem, bank-fixed)
// =================================================================================
__global__ __launch_bounds__(256, 2) void out_gemm(
    const float* __restrict__ Wo, const float* __restrict__ bo,
    float* __restrict__ out)
{
    __shared__ float As[2][8][132];
    __shared__ ull   Bsd[2][8][136];

    const int tid = threadIdx.x;
    const int m0 = blockIdx.y * 128;
    const int n0 = blockIdx.x * 128;

    const int ar  = tid >> 1;
    const int akq = (tid & 1) * 4;
    const float* Arow = g_hs + (size_t)(m0 + ar) * 1024;

    const int bkk = tid >> 5;
    const int bnq = (tid & 31) * 4;

    const int ty = tid >> 4;
    const int tx = tid & 15;

    ull acc[4][8];
    #pragma unroll
    for (int i = 0; i < 4; ++i)
        #pragma unroll
        for (int j = 0; j < 8; ++j) acc[i][j] = 0ull;

    {
        float4 av = *(const float4*)(Arow + akq);
        float4 bv = *(const float4*)(Wo + (size_t)bkk * 512 + n0 + bnq);
        As[0][akq + 0][ar] = av.x;
        As[0][akq + 1][ar] = av.y;
        As[0][akq + 2][ar] = av.z;
        As[0][akq + 3][ar] = av.w;
        Bsd[0][bkk][bslot(bnq + 0)] = pack2(bv.x);
        Bsd[0][bkk][bslot(bnq + 1)] = pack2(bv.y);
        Bsd[0][bkk][bslot(bnq + 2)] = pack2(bv.z);
        Bsd[0][bkk][bslot(bnq + 3)] = pack2(bv.w);
    }
    __syncthreads();

    int buf = 0;
    for (int k0 = 0; k0 < 1024; k0 += 8) {
        float4 av, bv;
        const bool more = (k0 + 8 < 1024);
        if (more) {
            av = *(const float4*)(Arow + k0 + 8 + akq);
            bv = *(const float4*)(Wo + (size_t)(k0 + 8 + bkk) * 512 + n0 + bnq);
        }

        #pragma unroll
        for (int k = 0; k < 8; ++k) {
            ulonglong2 a01 = *(const ulonglong2*)&As[buf][k][ty * 8];
            ulonglong2 a23 = *(const ulonglong2*)&As[buf][k][ty * 8 + 4];
            ull bd[8];
            #pragma unroll
            for (int j = 0; j < 8; ++j) bd[j] = Bsd[buf][k][j * 17 + tx];
            #pragma unroll
            for (int j = 0; j < 8; ++j) {
                acc[0][j] = ffma2(a01.x, bd[j], acc[0][j]);
                acc[1][j] = ffma2(a01.y, bd[j], acc[1][j]);
                acc[2][j] = ffma2(a23.x, bd[j], acc[2][j]);
                acc[3][j] = ffma2(a23.y, bd[j], acc[3][j]);
            }
        }

        if (more) {
            int nb = buf ^ 1;
            As[nb][akq + 0][ar] = av.x;
            As[nb][akq + 1][ar] = av.y;
            As[nb][akq + 2][ar] = av.z;
            As[nb][akq + 3][ar] = av.w;
            Bsd[nb][bkk][bslot(bnq + 0)] = pack2(bv.x);
            Bsd[nb][bkk][bslot(bnq + 1)] = pack2(bv.y);
            Bsd[nb][bkk][bslot(bnq + 2)] = pack2(bv.z);
            Bsd[nb][bkk][bslot(bnq + 3)] = pack2(bv.w);
            __syncthreads();
            buf = nb;
        }
    }

    const int og = n0 + tx * 8;
    float4 bl = *(const float4*)(bo + og);
    float4 bh = *(const float4*)(bo + og + 4);
    #pragma unroll
    for (int mp = 0; mp < 4; ++mp) {
        float2 v[8];
        #pragma unroll
        for (int j = 0; j < 8; ++j) v[j] = unpack2(acc[mp][j]);
        #pragma unroll
        for (int p = 0; p < 2; ++p) {
            int m = m0 + ty * 8 + mp * 2 + p;
            int tt = m >> 5, bb2 = m & 31;
            float* dst = out + ((size_t)bb2 * 512 + tt) * 512 + og;
            float4 o0, o1;
            o0.x = (p ? v[0].y : v[0].x) + bl.x;
            o0.y = (p ? v[1].y : v[1].x) + bl.y;
            o0.z = (p ? v[2].y : v[2].x) + bl.z;
            o0.w = (p ? v[3].y : v[3].x) + bl.w;
            o1.x = (p ? v[4].y : v[4].x) + bh.x;
            o1.y = (p ? v[5].y : v[5].x) + bh.y;
            o1.z = (p ? v[6].y : v[6].x) + bh.z;
            o1.w = (p ? v[7].y : v[7].x) + bh.w;
            *(float4*)dst = o0;
            *(float4*)(dst + 4) = o1;
        }
    }
}

// =================================================================================
extern "C" void kernel_launch(void* const* d_in, const int* in_sizes, int n_in,
                              void* d_out, int out_size)
{
    const float* X  = (const float*)d_in[0];
    const float* Wf = (const float*)d_in[1];
    const float* bf = (const float*)d_in[2];
    const float* Wb = (const float*)d_in[3];
    const float* bb = (const float*)d_in[4];
    const float* Wo = (const float*)d_in[5];
    const float* bo = (const float*)d_in[6];
    float* out = (float*)d_out;

    pre_gemm<<<dim3(8, 128), 256>>>(X, Wf, bf, Wb, bb);
    recur_kernel<<<128, 512>>>(Wf, Wb);
    out_gemm<<<dim3(4, 128), 256>>>(Wo, bo, out);
}

// round 12
// speedup vs baseline: 1.3380x; 1.0315x over previous
#include <cuda_runtime.h>
#include <cuda_bf16.h>
#include <math.h>
#include <stdint.h>

typedef unsigned long long ull;

// ---------------- scratch (static device globals; no allocation) ----------------
__device__ float g_pre[2u * 512u * 32u * 512u];   // [dir][t][b][c] 64MB
__device__ float g_hs[512u * 32u * 1024u];        // [t][b][dir*512+c] 64MB
__device__ unsigned int g_bar[16 * 32];           // per-(dir,grp) counters, 128B apart

// ---------------- f32x2 helpers ----------------
__device__ __forceinline__ ull ffma2(ull a, ull b, ull c) {
    ull d;
    asm("fma.rn.f32x2 %0, %1, %2, %3;" : "=l"(d) : "l"(a), "l"(b), "l"(c));
    return d;
}
__device__ __forceinline__ ull pack2(float x) {
    ull d;
    asm("mov.b64 %0, {%1, %1};" : "=l"(d) : "f"(x));
    return d;
}
__device__ __forceinline__ ull packab(float a, float b) {
    ull d;
    asm("mov.b64 %0, {%1, %2};" : "=l"(d) : "f"(a), "f"(b));
    return d;
}
__device__ __forceinline__ float2 unpack2(ull v) {
    float2 r;
    asm("mov.b64 {%0, %1}, %2;" : "=f"(r.x), "=f"(r.y) : "l"(v));
    return r;
}

// =================================================================================
// Kernel 1: pre-projection GEMM (double-buffered; N-paired accumulators:
//   acc[m][np] covers output columns (tx*8+2np, tx*8+2np+1); B pairs load
//   directly from smem as f32x2 — only A scalars are duplicated (8 movs/k, not 16))
// =================================================================================
__global__ __launch_bounds__(256, 2) void pre_gemm(
    const float* __restrict__ X,
    const float* __restrict__ Wf, const float* __restrict__ bf,
    const float* __restrict__ Wb, const float* __restrict__ bb)
{
    __shared__ float As[2][8][132];
    __shared__ float Bs[2][8][136];

    if (blockIdx.x == 0 && blockIdx.y == 0 && threadIdx.x < 16)
        g_bar[threadIdx.x * 32] = 0u;

    const int tid = threadIdx.x;
    const int m0 = blockIdx.y * 128;
    const int n0 = blockIdx.x * 128;
    const int dir = n0 >> 9;
    const int c0 = n0 & 511;
    const float* Bmat = dir ? Wb : Wf;
    const float* bias = dir ? bb : bf;

    const int ar  = tid >> 1;
    const int akq = (tid & 1) * 4;
    const int am  = m0 + ar;
    const float* Arow = X + ((size_t)(am & 31) * 512 + (size_t)(am >> 5)) * 512;

    const int bkk = tid >> 5;
    const int bnq = (tid & 31) * 4;

    const int ty = tid >> 4;
    const int tx = tid & 15;

    ull acc[8][4];   // [m][n-pair]
    #pragma unroll
    for (int i = 0; i < 8; ++i)
        #pragma unroll
        for (int j = 0; j < 4; ++j) acc[i][j] = 0ull;

    {
        float4 av = *(const float4*)(Arow + akq);
        float4 bv = *(const float4*)(Bmat + (size_t)bkk * 512 + c0 + bnq);
        As[0][akq + 0][ar] = av.x;
        As[0][akq + 1][ar] = av.y;
        As[0][akq + 2][ar] = av.z;
        As[0][akq + 3][ar] = av.w;
        *(float4*)&Bs[0][bkk][bnq] = bv;
    }
    __syncthreads();

    int buf = 0;
    for (int k0 = 0; k0 < 512; k0 += 8) {
        float4 av, bv;
        const bool more = (k0 + 8 < 512);
        if (more) {
            av = *(const float4*)(Arow + k0 + 8 + akq);
            bv = *(const float4*)(Bmat + (size_t)(k0 + 8 + bkk) * 512 + c0 + bnq);
        }

        #pragma unroll
        for (int k = 0; k < 8; ++k) {
            float4 aA = *(const float4*)&As[buf][k][ty * 8];
            float4 aB = *(const float4*)&As[buf][k][ty * 8 + 4];
            ulonglong2 b01 = *(const ulonglong2*)&Bs[buf][k][tx * 8];
            ulonglong2 b23 = *(const ulonglong2*)&Bs[buf][k][tx * 8 + 4];
            ull ad[8];
            ad[0] = pack2(aA.x); ad[1] = pack2(aA.y);
            ad[2] = pack2(aA.z); ad[3] = pack2(aA.w);
            ad[4] = pack2(aB.x); ad[5] = pack2(aB.y);
            ad[6] = pack2(aB.z); ad[7] = pack2(aB.w);
            #pragma unroll
            for (int m = 0; m < 8; ++m) {
                acc[m][0] = ffma2(ad[m], b01.x, acc[m][0]);
                acc[m][1] = ffma2(ad[m], b01.y, acc[m][1]);
                acc[m][2] = ffma2(ad[m], b23.x, acc[m][2]);
                acc[m][3] = ffma2(ad[m], b23.y, acc[m][3]);
            }
        }

        if (more) {
            int nb = buf ^ 1;
            As[nb][akq + 0][ar] = av.x;
            As[nb][akq + 1][ar] = av.y;
            As[nb][akq + 2][ar] = av.z;
            As[nb][akq + 3][ar] = av.w;
            *(float4*)&Bs[nb][bkk][bnq] = bv;
            __syncthreads();
            buf = nb;
        }
    }

    // epilogue: acc[m] holds 8 consecutive output columns cg..cg+7
    const int cg = c0 + tx * 8;
    float4 bl = *(const float4*)(bias + cg);
    float4 bh = *(const float4*)(bias + cg + 4);
    #pragma unroll
    for (int m = 0; m < 8; ++m) {
        float2 p0 = unpack2(acc[m][0]);
        float2 p1 = unpack2(acc[m][1]);
        float2 p2 = unpack2(acc[m][2]);
        float2 p3 = unpack2(acc[m][3]);
        int gm = m0 + ty * 8 + m;
        int tt = gm >> 5, bb2 = gm & 31;
        float* dst = g_pre + ((size_t)dir * 512 + tt) * 16384 + (size_t)bb2 * 512 + cg;
        float4 o0, o1;
        o0.x = p0.x + bl.x; o0.y = p0.y + bl.y;
        o0.z = p1.x + bl.z; o0.w = p1.y + bl.w;
        o1.x = p2.x + bh.x; o1.y = p2.y + bh.y;
        o1.z = p3.x + bh.z; o1.w = p3.y + bh.w;
        *(float4*)dst = o0;
        *(float4*)(dst + 4) = o1;
    }
}

// =================================================================================
// Kernel 2: persistent bidirectional recurrence (R6 v6 + spin backoff safeguard)
//   128 CTAs = 2 dirs x 8 batch-groups(4) x 8 col-slices(64), 512 threads.
// =================================================================================
__global__ __launch_bounds__(512) void recur_kernel(
    const float* __restrict__ Wf, const float* __restrict__ Wb)
{
    __shared__ float s_h[4 * 520];      // [4 batches][512+8]
    __shared__ float s_red[8 * 256];    // [ks][b*64+c]

    const int tid = threadIdx.x;
    const int bx  = blockIdx.x;
    const int dir = bx & 1;
    const int grp = (bx >> 1) & 7;          // batch group 0..7 (4 batches)
    const int sl  = bx >> 4;                // col slice 0..7 (64 cols)
    const int c0  = sl * 64;
    const int bgl = grp * 4;
    const float* W = dir ? Wb : Wf;

    const int c  = tid & 63;
    const int ks = tid >> 6;

    // Wh column (c0+c), k in [ks*64, ks*64+64) -> 32 f32x2 regs
    ull wreg[16][2];
    #pragma unroll
    for (int j = 0; j < 16; ++j) {
        int k = ks * 64 + j * 4;
        const float* wp = W + (size_t)(512 + k) * 512 + c0 + c;
        wreg[j][0] = packab(wp[0],    wp[512]);
        wreg[j][1] = packab(wp[1024], wp[1536]);
    }

    // staging: 512 float4s, one per thread
    const int sb   = tid >> 7;              // batch row 0..3
    const int soff = (tid & 127) * 4;       // float offset in 512-row

    // reduce/store map (tid < 256): batch rb, col rc
    const int rb = tid >> 6;
    const int rc = tid & 63;

    unsigned int* bar = &g_bar[(dir * 8 + grp) * 32];

    // first step's pre-activation
    float pre = 0.f;
    {
        const int t0 = dir ? 511 : 0;
        if (tid < 256)
            pre = __ldcg(&g_pre[((size_t)dir * 512 + t0) * 16384 +
                                (size_t)(bgl + rb) * 512 + c0 + rc]);
    }

    for (int s = 0; s < 512; ++s) {
        const int t = dir ? (511 - s) : s;

        float hval = 0.f;
        if (s == 0) {
            if (tid < 256) hval = tanhf(pre);
        } else {
            const int tp = dir ? (t + 1) : (t - 1);
            const float* hbase = g_hs + (size_t)tp * 32 * 1024 +
                                 (size_t)bgl * 1024 + dir * 512;

            // stage the group's 4 h rows (8KB) in one shot
            float4 v0 = __ldcg((const float4*)(hbase + sb * 1024 + soff));
            *(float4*)&s_h[sb * 520 + soff] = v0;
            __syncthreads();

            // mat-vec partials: smem reads warp-broadcast (address = f(b,ks) only)
            ull acc[4] = {0ull, 0ull, 0ull, 0ull};
            #pragma unroll
            for (int b = 0; b < 4; ++b) {
                const ulonglong2* hp = (const ulonglong2*)&s_h[b * 520 + ks * 64];
                #pragma unroll
                for (int j = 0; j < 16; ++j) {
                    ulonglong2 h2 = hp[j];
                    acc[b] = ffma2(h2.x, wreg[j][0], acc[b]);
                    acc[b] = ffma2(h2.y, wreg[j][1], acc[b]);
                }
            }
            #pragma unroll
            for (int b = 0; b < 4; ++b) {
                float2 p = unpack2(acc[b]);
                s_red[ks * 256 + b * 64 + c] = p.x + p.y;
            }
            __syncthreads();

            if (tid < 256) {
                float sum = pre;
                #pragma unroll
                for (int k8 = 0; k8 < 8; ++k8) sum += s_red[k8 * 256 + tid];
                hval = tanhf(sum);
            }
        }

        if (tid < 256)
            __stcg(&g_hs[((size_t)t * 32 + bgl + rb) * 1024 +
                         dir * 512 + c0 + rc], hval);

        if (s < 511) {
            __syncthreads();   // CTA-HB: all h stores ordered before thread0's release
            if (tid == 0)
                asm volatile("red.release.gpu.global.add.u32 [%0], 1;"
                             :: "l"(bar) : "memory");
            // prefetch next step's pre under the barrier
            const int tn = dir ? (510 - s) : (s + 1);
            float npre = 0.f;
            if (tid < 256)
                npre = __ldcg(&g_pre[((size_t)dir * 512 + tn) * 16384 +
                                     (size_t)(bgl + rb) * 512 + c0 + rc]);
            if (tid == 0) {
                const unsigned target = (unsigned)(s + 1) * 8u;
                unsigned v;
                int spins = 0;
                for (;;) {
                    asm volatile("ld.acquire.gpu.global.u32 %0, [%1];"
                                 : "=r"(v) : "l"(bar) : "memory");
                    if (v >= target) break;
                    if (++spins > 2048) __nanosleep(64);   // safety backoff only
                }
            }
            __syncthreads();
            pre = npre;
        }
    }
}

// =================================================================================
// Kernel 3: output GEMM (double-buffered; N-paired accumulators)
// =================================================================================
__global__ __launch_bounds__(256, 2) void out_gemm(
    const float* __restrict__ Wo, const float* __restrict__ bo,
    float* __restrict__ out)
{
    __shared__ float As[2][8][132];
    __shared__ float Bs[2][8][136];

    const int tid = threadIdx.x;
    const int m0 = blockIdx.y * 128;
    const int n0 = blockIdx.x * 128;

    const int ar  = tid >> 1;
    const int akq = (tid & 1) * 4;
    const float* Arow = g_hs + (size_t)(m0 + ar) * 1024;

    const int bkk = tid >> 5;
    const int bnq = (tid & 31) * 4;

    const int ty = tid >> 4;
    const int tx = tid & 15;

    ull acc[8][4];
    #pragma unroll
    for (int i = 0; i < 8; ++i)
        #pragma unroll
        for (int j = 0; j < 4; ++j) acc[i][j] = 0ull;

    {
        float4 av = *(const float4*)(Arow + akq);
        float4 bv = *(const float4*)(Wo + (size_t)bkk * 512 + n0 + bnq);
        As[0][akq + 0][ar] = av.x;
        As[0][akq + 1][ar] = av.y;
        As[0][akq + 2][ar] = av.z;
        As[0][akq + 3][ar] = av.w;
        *(float4*)&Bs[0][bkk][bnq] = bv;
    }
    __syncthreads();

    int buf = 0;
    for (int k0 = 0; k0 < 1024; k0 += 8) {
        float4 av, bv;
        const bool more = (k0 + 8 < 1024);
        if (more) {
            av = *(const float4*)(Arow + k0 + 8 + akq);
            bv = *(const float4*)(Wo + (size_t)(k0 + 8 + bkk) * 512 + n0 + bnq);
        }

        #pragma unroll
        for (int k = 0; k < 8; ++k) {
            float4 aA = *(const float4*)&As[buf][k][ty * 8];
            float4 aB = *(const float4*)&As[buf][k][ty * 8 + 4];
            ulonglong2 b01 = *(const ulonglong2*)&Bs[buf][k][tx * 8];
            ulonglong2 b23 = *(const ulonglong2*)&Bs[buf][k][tx * 8 + 4];
            ull ad[8];
            ad[0] = pack2(aA.x); ad[1] = pack2(aA.y);
            ad[2] = pack2(aA.z); ad[3] = pack2(aA.w);
            ad[4] = pack2(aB.x); ad[5] = pack2(aB.y);
            ad[6] = pack2(aB.z); ad[7] = pack2(aB.w);
            #pragma unroll
            for (int m = 0; m < 8; ++m) {
                acc[m][0] = ffma2(ad[m], b01.x, acc[m][0]);
                acc[m][1] = ffma2(ad[m], b01.y, acc[m][1]);
                acc[m][2] = ffma2(ad[m], b23.x, acc[m][2]);
                acc[m][3] = ffma2(ad[m], b23.y, acc[m][3]);
            }
        }

        if (more) {
            int nb = buf ^ 1;
            As[nb][akq + 0][ar] = av.x;
            As[nb][akq + 1][ar] = av.y;
            As[nb][akq + 2][ar] = av.z;
            As[nb][akq + 3][ar] = av.w;
            *(float4*)&Bs[nb][bkk][bnq] = bv;
            __syncthreads();
            buf = nb;
        }
    }

    const int og = n0 + tx * 8;
    float4 bl = *(const float4*)(bo + og);
    float4 bh = *(const float4*)(bo + og + 4);
    #pragma unroll
    for (int m = 0; m < 8; ++m) {
        float2 p0 = unpack2(acc[m][0]);
        float2 p1 = unpack2(acc[m][1]);
        float2 p2 = unpack2(acc[m][2]);
        float2 p3 = unpack2(acc[m][3]);
        int gm = m0 + ty * 8 + m;
        int tt = gm >> 5, bb2 = gm & 31;
        float* dst = out + ((size_t)bb2 * 512 + tt) * 512 + og;
        float4 o0, o1;
        o0.x = p0.x + bl.x; o0.y = p0.y + bl.y;
        o0.z = p1.x + bl.z; o0.w = p1.y + bl.w;
        o1.x = p2.x + bh.x; o1.y = p2.y + bh.y;
        o1.z = p3.x + bh.z; o1.w = p3.y + bh.w;
        *(float4*)dst = o0;
        *(float4*)(dst + 4) = o1;
    }
}

// =================================================================================
extern "C" void kernel_launch(void* const* d_in, const int* in_sizes, int n_in,
                              void* d_out, int out_size)
{
    const float* X  = (const float*)d_in[0];
    const float* Wf = (const float*)d_in[1];
    const float* bf = (const float*)d_in[2];
    const float* Wb = (const float*)d_in[3];
    const float* bb = (const float*)d_in[4];
    const float* Wo = (const float*)d_in[5];
    const float* bo = (const float*)d_in[6];
    float* out = (float*)d_out;

    pre_gemm<<<dim3(8, 128), 256>>>(X, Wf, bf, Wb, bb);
    recur_kernel<<<128, 512>>>(Wf, Wb);
    out_gemm<<<dim3(4, 128), 256>>>(Wo, bo, out);
}

// round 13
// speedup vs baseline: 1.3417x; 1.0028x over previous
#include <cuda_runtime.h>
#include <cuda_bf16.h>
#include <math.h>
#include <stdint.h>

typedef unsigned long long ull;

// ---------------- scratch (static device globals; no allocation) ----------------
__device__ float g_pre[2u * 512u * 32u * 512u];   // [dir][t][b][c] 64MB
__device__ float g_hs[512u * 32u * 1024u];        // [t][b][dir*512+c] 64MB
__device__ unsigned int g_bar[16 * 32];           // per-(dir,grp) counters, 128B apart

// ---------------- f32x2 helpers ----------------
__device__ __forceinline__ ull ffma2(ull a, ull b, ull c) {
    ull d;
    asm("fma.rn.f32x2 %0, %1, %2, %3;" : "=l"(d) : "l"(a), "l"(b), "l"(c));
    return d;
}
__device__ __forceinline__ ull pack2(float x) {
    ull d;
    asm("mov.b64 %0, {%1, %1};" : "=l"(d) : "f"(x));
    return d;
}
__device__ __forceinline__ ull packab(float a, float b) {
    ull d;
    asm("mov.b64 %0, {%1, %2};" : "=l"(d) : "f"(a), "f"(b));
    return d;
}
__device__ __forceinline__ float2 unpack2(ull v) {
    float2 r;
    asm("mov.b64 {%0, %1}, %2;" : "=f"(r.x), "=f"(r.y) : "l"(v));
    return r;
}

// =================================================================================
// Kernel 1: pre-projection GEMM (R12 verbatim: double-buffered, N-paired acc)
// =================================================================================
__global__ __launch_bounds__(256, 2) void pre_gemm(
    const float* __restrict__ X,
    const float* __restrict__ Wf, const float* __restrict__ bf,
    const float* __restrict__ Wb, const float* __restrict__ bb)
{
    __shared__ float As[2][8][132];
    __shared__ float Bs[2][8][136];

    if (blockIdx.x == 0 && blockIdx.y == 0 && threadIdx.x < 16)
        g_bar[threadIdx.x * 32] = 0u;

    const int tid = threadIdx.x;
    const int m0 = blockIdx.y * 128;
    const int n0 = blockIdx.x * 128;
    const int dir = n0 >> 9;
    const int c0 = n0 & 511;
    const float* Bmat = dir ? Wb : Wf;
    const float* bias = dir ? bb : bf;

    const int ar  = tid >> 1;
    const int akq = (tid & 1) * 4;
    const int am  = m0 + ar;
    const float* Arow = X + ((size_t)(am & 31) * 512 + (size_t)(am >> 5)) * 512;

    const int bkk = tid >> 5;
    const int bnq = (tid & 31) * 4;

    const int ty = tid >> 4;
    const int tx = tid & 15;

    ull acc[8][4];   // [m][n-pair]
    #pragma unroll
    for (int i = 0; i < 8; ++i)
        #pragma unroll
        for (int j = 0; j < 4; ++j) acc[i][j] = 0ull;

    {
        float4 av = *(const float4*)(Arow + akq);
        float4 bv = *(const float4*)(Bmat + (size_t)bkk * 512 + c0 + bnq);
        As[0][akq + 0][ar] = av.x;
        As[0][akq + 1][ar] = av.y;
        As[0][akq + 2][ar] = av.z;
        As[0][akq + 3][ar] = av.w;
        *(float4*)&Bs[0][bkk][bnq] = bv;
    }
    __syncthreads();

    int buf = 0;
    for (int k0 = 0; k0 < 512; k0 += 8) {
        float4 av, bv;
        const bool more = (k0 + 8 < 512);
        if (more) {
            av = *(const float4*)(Arow + k0 + 8 + akq);
            bv = *(const float4*)(Bmat + (size_t)(k0 + 8 + bkk) * 512 + c0 + bnq);
        }

        #pragma unroll
        for (int k = 0; k < 8; ++k) {
            float4 aA = *(const float4*)&As[buf][k][ty * 8];
            float4 aB = *(const float4*)&As[buf][k][ty * 8 + 4];
            ulonglong2 b01 = *(const ulonglong2*)&Bs[buf][k][tx * 8];
            ulonglong2 b23 = *(const ulonglong2*)&Bs[buf][k][tx * 8 + 4];
            ull ad[8];
            ad[0] = pack2(aA.x); ad[1] = pack2(aA.y);
            ad[2] = pack2(aA.z); ad[3] = pack2(aA.w);
            ad[4] = pack2(aB.x); ad[5] = pack2(aB.y);
            ad[6] = pack2(aB.z); ad[7] = pack2(aB.w);
            #pragma unroll
            for (int m = 0; m < 8; ++m) {
                acc[m][0] = ffma2(ad[m], b01.x, acc[m][0]);
                acc[m][1] = ffma2(ad[m], b01.y, acc[m][1]);
                acc[m][2] = ffma2(ad[m], b23.x, acc[m][2]);
                acc[m][3] = ffma2(ad[m], b23.y, acc[m][3]);
            }
        }

        if (more) {
            int nb = buf ^ 1;
            As[nb][akq + 0][ar] = av.x;
            As[nb][akq + 1][ar] = av.y;
            As[nb][akq + 2][ar] = av.z;
            As[nb][akq + 3][ar] = av.w;
            *(float4*)&Bs[nb][bkk][bnq] = bv;
            __syncthreads();
            buf = nb;
        }
    }

    const int cg = c0 + tx * 8;
    float4 bl = *(const float4*)(bias + cg);
    float4 bh = *(const float4*)(bias + cg + 4);
    #pragma unroll
    for (int m = 0; m < 8; ++m) {
        float2 p0 = unpack2(acc[m][0]);
        float2 p1 = unpack2(acc[m][1]);
        float2 p2 = unpack2(acc[m][2]);
        float2 p3 = unpack2(acc[m][3]);
        int gm = m0 + ty * 8 + m;
        int tt = gm >> 5, bb2 = gm & 31;
        float* dst = g_pre + ((size_t)dir * 512 + tt) * 16384 + (size_t)bb2 * 512 + cg;
        float4 o0, o1;
        o0.x = p0.x + bl.x; o0.y = p0.y + bl.y;
        o0.z = p1.x + bl.z; o0.w = p1.y + bl.w;
        o1.x = p2.x + bh.x; o1.y = p2.y + bh.y;
        o1.z = p3.x + bh.z; o1.w = p3.y + bh.w;
        *(float4*)dst = o0;
        *(float4*)(dst + 4) = o1;
    }
}

// =================================================================================
// Kernel 2: persistent bidirectional recurrence (v10 — warp-autonomous detect)
//   128 CTAs = 2 dirs x 8 batch-groups(4) x 8 col-slices(64), 512 threads.
//   Barrier: full-CTA sync -> thread0 red.release; then EACH WARP's lane0 polls
//   the counter independently (ld.acquire + backoff), __syncwarp, and the warp
//   starts its staging LDGs immediately — no CTA-wide broadcast hop.
// =================================================================================
__global__ __launch_bounds__(512) void recur_kernel(
    const float* __restrict__ Wf, const float* __restrict__ Wb)
{
    __shared__ float s_h[4 * 520];      // [4 batches][512+8]
    __shared__ float s_red[8 * 256];    // [ks][b*64+c]

    const int tid = threadIdx.x;
    const int bx  = blockIdx.x;
    const int dir = bx & 1;
    const int grp = (bx >> 1) & 7;          // batch group 0..7 (4 batches)
    const int sl  = bx >> 4;                // col slice 0..7 (64 cols)
    const int c0  = sl * 64;
    const int bgl = grp * 4;
    const float* W = dir ? Wb : Wf;

    const int c  = tid & 63;
    const int ks = tid >> 6;

    // Wh column (c0+c), k in [ks*64, ks*64+64) -> 32 f32x2 regs
    ull wreg[16][2];
    #pragma unroll
    for (int j = 0; j < 16; ++j) {
        int k = ks * 64 + j * 4;
        const float* wp = W + (size_t)(512 + k) * 512 + c0 + c;
        wreg[j][0] = packab(wp[0],    wp[512]);
        wreg[j][1] = packab(wp[1024], wp[1536]);
    }

    // staging: 512 float4s, one per thread
    const int sb   = tid >> 7;              // batch row 0..3
    const int soff = (tid & 127) * 4;       // float offset in 512-row

    // reduce/store map (tid < 256): batch rb, col rc
    const int rb = tid >> 6;
    const int rc = tid & 63;

    unsigned int* bar = &g_bar[(dir * 8 + grp) * 32];

    // first step's pre-activation
    float pre = 0.f;
    {
        const int t0 = dir ? 511 : 0;
        if (tid < 256)
            pre = __ldcg(&g_pre[((size_t)dir * 512 + t0) * 16384 +
                                (size_t)(bgl + rb) * 512 + c0 + rc]);
    }

    for (int s = 0; s < 512; ++s) {
        const int t = dir ? (511 - s) : s;

        float hval = 0.f;
        if (s == 0) {
            if (tid < 256) hval = tanhf(pre);
        } else {
            const int tp = dir ? (t + 1) : (t - 1);
            const float* hbase = g_hs + (size_t)tp * 32 * 1024 +
                                 (size_t)bgl * 1024 + dir * 512;

            // stage the group's 4 h rows (8KB); warp proceeds as soon as ITS
            // detect (end of previous iteration) fired
            float4 v0 = __ldcg((const float4*)(hbase + sb * 1024 + soff));
            *(float4*)&s_h[sb * 520 + soff] = v0;
            __syncthreads();

            // mat-vec partials: smem reads warp-broadcast (address = f(b,ks) only)
            ull acc[4] = {0ull, 0ull, 0ull, 0ull};
            #pragma unroll
            for (int b = 0; b < 4; ++b) {
                const ulonglong2* hp = (const ulonglong2*)&s_h[b * 520 + ks * 64];
                #pragma unroll
                for (int j = 0; j < 16; ++j) {
                    ulonglong2 h2 = hp[j];
                    acc[b] = ffma2(h2.x, wreg[j][0], acc[b]);
                    acc[b] = ffma2(h2.y, wreg[j][1], acc[b]);
                }
            }
            #pragma unroll
            for (int b = 0; b < 4; ++b) {
                float2 p = unpack2(acc[b]);
                s_red[ks * 256 + b * 64 + c] = p.x + p.y;
            }
            __syncthreads();

            if (tid < 256) {
                float sum = pre;
                #pragma unroll
                for (int k8 = 0; k8 < 8; ++k8) sum += s_red[k8 * 256 + tid];
                hval = tanhf(sum);
            }
        }

        if (tid < 256)
            __stcg(&g_hs[((size_t)t * 32 + bgl + rb) * 1024 +
                         dir * 512 + c0 + rc], hval);

        if (s < 511) {
            __syncthreads();   // CTA-HB: all h stores ordered before thread0's release
            if (tid == 0)
                asm volatile("red.release.gpu.global.add.u32 [%0], 1;"
                             :: "l"(bar) : "memory");
            // prefetch next step's pre (independent of the poll)
            const int tn = dir ? (510 - s) : (s + 1);
            float npre = 0.f;
            if (tid < 256)
                npre = __ldcg(&g_pre[((size_t)dir * 512 + tn) * 16384 +
                                     (size_t)(bgl + rb) * 512 + c0 + rc]);
            // warp-autonomous detect: lane0 of each warp polls, then syncwarp
            if ((tid & 31) == 0) {
                const unsigned target = (unsigned)(s + 1) * 8u;
                unsigned v;
                int spins = 0;
                for (;;) {
                    asm volatile("ld.acquire.gpu.global.u32 %0, [%1];"
                                 : "=r"(v) : "l"(bar) : "memory");
                    if (v >= target) break;
                    if (++spins > 2048) __nanosleep(64);   // safety backoff only
                }
            }
            __syncwarp();      // orders lane0's acquire before this warp's h loads
            pre = npre;
        }
    }
}

// =================================================================================
// Kernel 3: output GEMM (R12 verbatim: double-buffered, N-paired acc)
// =================================================================================
__global__ __launch_bounds__(256, 2) void out_gemm(
    const float* __restrict__ Wo, const float* __restrict__ bo,
    float* __restrict__ out)
{
    __shared__ float As[2][8][132];
    __shared__ float Bs[2][8][136];

    const int tid = threadIdx.x;
    const int m0 = blockIdx.y * 128;
    const int n0 = blockIdx.x * 128;

    const int ar  = tid >> 1;
    const int akq = (tid & 1) * 4;
    const float* Arow = g_hs + (size_t)(m0 + ar) * 1024;

    const int bkk = tid >> 5;
    const int bnq = (tid & 31) * 4;

    const int ty = tid >> 4;
    const int tx = tid & 15;

    ull acc[8][4];
    #pragma unroll
    for (int i = 0; i < 8; ++i)
        #pragma unroll
        for (int j = 0; j < 4; ++j) acc[i][j] = 0ull;

    {
        float4 av = *(const float4*)(Arow + akq);
        float4 bv = *(const float4*)(Wo + (size_t)bkk * 512 + n0 + bnq);
        As[0][akq + 0][ar] = av.x;
        As[0][akq + 1][ar] = av.y;
        As[0][akq + 2][ar] = av.z;
        As[0][akq + 3][ar] = av.w;
        *(float4*)&Bs[0][bkk][bnq] = bv;
    }
    __syncthreads();

    int buf = 0;
    for (int k0 = 0; k0 < 1024; k0 += 8) {
        float4 av, bv;
        const bool more = (k0 + 8 < 1024);
        if (more) {
            av = *(const float4*)(Arow + k0 + 8 + akq);
            bv = *(const float4*)(Wo + (size_t)(k0 + 8 + bkk) * 512 + n0 + bnq);
        }

        #pragma unroll
        for (int k = 0; k < 8; ++k) {
            float4 aA = *(const float4*)&As[buf][k][ty * 8];
            float4 aB = *(const float4*)&As[buf][k][ty * 8 + 4];
            ulonglong2 b01 = *(const ulonglong2*)&Bs[buf][k][tx * 8];
            ulonglong2 b23 = *(const ulonglong2*)&Bs[buf][k][tx * 8 + 4];
            ull ad[8];
            ad[0] = pack2(aA.x); ad[1] = pack2(aA.y);
            ad[2] = pack2(aA.z); ad[3] = pack2(aA.w);
            ad[4] = pack2(aB.x); ad[5] = pack2(aB.y);
            ad[6] = pack2(aB.z); ad[7] = pack2(aB.w);
            #pragma unroll
            for (int m = 0; m < 8; ++m) {
                acc[m][0] = ffma2(ad[m], b01.x, acc[m][0]);
                acc[m][1] = ffma2(ad[m], b01.y, acc[m][1]);
                acc[m][2] = ffma2(ad[m], b23.x, acc[m][2]);
                acc[m][3] = ffma2(ad[m], b23.y, acc[m][3]);
            }
        }

        if (more) {
            int nb = buf ^ 1;
            As[nb][akq + 0][ar] = av.x;
            As[nb][akq + 1][ar] = av.y;
            As[nb][akq + 2][ar] = av.z;
            As[nb][akq + 3][ar] = av.w;
            *(float4*)&Bs[nb][bkk][bnq] = bv;
            __syncthreads();
            buf = nb;
        }
    }

    const int og = n0 + tx * 8;
    float4 bl = *(const float4*)(bo + og);
    float4 bh = *(const float4*)(bo + og + 4);
    #pragma unroll
    for (int m = 0; m < 8; ++m) {
        float2 p0 = unpack2(acc[m][0]);
        float2 p1 = unpack2(acc[m][1]);
        float2 p2 = unpack2(acc[m][2]);
        float2 p3 = unpack2(acc[m][3]);
        int gm = m0 + ty * 8 + m;
        int tt = gm >> 5, bb2 = gm & 31;
        float* dst = out + ((size_t)bb2 * 512 + tt) * 512 + og;
        float4 o0, o1;
        o0.x = p0.x + bl.x; o0.y = p0.y + bl.y;
        o0.z = p1.x + bl.z; o0.w = p1.y + bl.w;
        o1.x = p2.x + bh.x; o1.y = p2.y + bh.y;
        o1.z = p3.x + bh.z; o1.w = p3.y + bh.w;
        *(float4*)dst = o0;
        *(float4*)(dst + 4) = o1;
    }
}

// =================================================================================
extern "C" void kernel_launch(void* const* d_in, const int* in_sizes, int n_in,
                              void* d_out, int out_size)
{
    const float* X  = (const float*)d_in[0];
    const float* Wf = (const float*)d_in[1];
    const float* bf = (const float*)d_in[2];
    const float* Wb = (const float*)d_in[3];
    const float* bb = (const float*)d_in[4];
    const float* Wo = (const float*)d_in[5];
    const float* bo = (const float*)d_in[6];
    float* out = (float*)d_out;

    pre_gemm<<<dim3(8, 128), 256>>>(X, Wf, bf, Wb, bb);
    recur_kernel<<<128, 512>>>(Wf, Wb);
    out_gemm<<<dim3(4, 128), 256>>>(Wo, bo, out);
}